// round 1
// baseline (speedup 1.0000x reference)
#include <cuda_runtime.h>
#include <math.h>

#define Bb 2
#define Ss 2048
#define Dd 1024
#define Hh 16
#define DKk 64

// Scratch (device globals: allocation-free rule)
__device__ float g_q[(size_t)Bb * Hh * Ss * DKk];   // [B,H,S,DK]
__device__ float g_k[(size_t)Bb * Hh * Ss * DKk];
__device__ float g_v[(size_t)Bb * Hh * Ss * DKk];
__device__ float g_att[(size_t)Bb * Ss * Dd];       // [B,S,D]

// ---------------------------------------------------------------------------
// GEMM: C = A[M x 1024] @ W[1024 x 1024] + bias.  M = 4096.
// head_split=1: write to [B,H,S,DK] layout; else row-major [M, 1024].
// Block tile 64x64, K-tile 16, 256 threads, 4x4 per-thread microtile.
// ---------------------------------------------------------------------------
__global__ __launch_bounds__(256) void gemm_bias_kernel(
    const float* __restrict__ A, const float* __restrict__ W,
    const float* __restrict__ bias, float* __restrict__ C, int head_split)
{
    __shared__ float Ast[16][65];   // [k][m] (A transposed)
    __shared__ float Bs[16][65];    // [k][n]

    const int tid = threadIdx.x;
    const int bn = blockIdx.x * 64;
    const int bm = blockIdx.y * 64;
    const int ty = tid >> 4;   // 0..15  (M direction)
    const int tx = tid & 15;   // 0..15  (N direction)

    float acc[4][4];
    #pragma unroll
    for (int i = 0; i < 4; i++)
        #pragma unroll
        for (int j = 0; j < 4; j++) acc[i][j] = 0.f;

    const int a_row = tid >> 2;          // 0..63
    const int a_kq  = (tid & 3) * 4;     // 0,4,8,12
    const int w_k   = tid >> 4;          // 0..15
    const int w_nq  = (tid & 15) * 4;    // 0..60

    const float* Aptr = A + (size_t)(bm + a_row) * 1024 + a_kq;
    const float* Wptr = W + (size_t)w_k * 1024 + bn + w_nq;

    for (int k0 = 0; k0 < 1024; k0 += 16) {
        float4 av = *(const float4*)(Aptr + k0);
        Ast[a_kq + 0][a_row] = av.x;
        Ast[a_kq + 1][a_row] = av.y;
        Ast[a_kq + 2][a_row] = av.z;
        Ast[a_kq + 3][a_row] = av.w;
        float4 wv = *(const float4*)(Wptr + (size_t)k0 * 1024);
        Bs[w_k][w_nq + 0] = wv.x;
        Bs[w_k][w_nq + 1] = wv.y;
        Bs[w_k][w_nq + 2] = wv.z;
        Bs[w_k][w_nq + 3] = wv.w;
        __syncthreads();

        #pragma unroll
        for (int kk = 0; kk < 16; kk++) {
            float a[4], b[4];
            #pragma unroll
            for (int i = 0; i < 4; i++) a[i] = Ast[kk][ty * 4 + i];
            #pragma unroll
            for (int j = 0; j < 4; j++) b[j] = Bs[kk][tx * 4 + j];
            #pragma unroll
            for (int i = 0; i < 4; i++)
                #pragma unroll
                for (int j = 0; j < 4; j++)
                    acc[i][j] = fmaf(a[i], b[j], acc[i][j]);
        }
        __syncthreads();
    }

    #pragma unroll
    for (int i = 0; i < 4; i++) {
        const int m = bm + ty * 4 + i;
        #pragma unroll
        for (int j = 0; j < 4; j++) {
            const int n = bn + tx * 4 + j;
            float v = acc[i][j] + bias[n];
            if (head_split) {
                const int b = m >> 11;          // m / S
                const int s = m & (Ss - 1);     // m % S
                const int h = n >> 6;           // n / DK
                const int d = n & (DKk - 1);    // n % DK
                C[(((size_t)b * Hh + h) * Ss + s) * DKk + d] = v;
            } else {
                C[(size_t)m * Dd + n] = v;
            }
        }
    }
}

// ---------------------------------------------------------------------------
// RoPE (matches the reference's concatenated-freq / interleaved-pair variant):
//   out[2i]   = x[2i]*cos(th(2i))   - x[2i+1]*sin(th(2i+1))
//   out[2i+1] = x[2i]*sin(th(2i))   + x[2i+1]*cos(th(2i+1))
//   th(d) = s * inv_freq[d mod 32],  inv_freq[j] = 1/10000^(j/32)
// Tensor layout [B*H, S, DK]; one thread per pair.
// ---------------------------------------------------------------------------
__global__ void rope_kernel(float* __restrict__ x, int total_pairs)
{
    int idx = blockIdx.x * blockDim.x + threadIdx.x;
    if (idx >= total_pairs) return;
    const int i  = idx & 31;                 // pair 0..31
    const int s  = (idx >> 5) & (Ss - 1);    // position
    const int bh = idx >> 16;                // 32 pairs * 2048 pos = 2^16

    float* p = x + (((size_t)bh * Ss + s) * DKk) + 2 * i;
    const float x0 = p[0], x1 = p[1];

    const int j0 = (2 * i) & 31;
    const int j1 = (2 * i + 1) & 31;
    const float inv0 = 1.0f / powf(10000.0f, (float)j0 * (1.0f / 32.0f));
    const float inv1 = 1.0f / powf(10000.0f, (float)j1 * (1.0f / 32.0f));
    const float a0 = (float)s * inv0;
    const float a1 = (float)s * inv1;
    float s0, c0, s1, c1;
    sincosf(a0, &s0, &c0);
    sincosf(a1, &s1, &c1);
    p[0] = x0 * c0 - x1 * s1;
    p[1] = x0 * s0 + x1 * c1;
}

// ---------------------------------------------------------------------------
// Causal flash attention, fp32. One block = 64 queries of one (b,h).
// Key blocks of 64 streamed with online softmax. 256 threads, 4x4 tiles.
// Dynamic SMEM: Qt[64][65] (d-major), Kt[64][65] (d-major), Vs[64][65],
// Ps[64][64].
// ---------------------------------------------------------------------------
__global__ __launch_bounds__(256) void attn_kernel()
{
    extern __shared__ float smem[];
    float (*Qt)[65] = (float(*)[65])(smem);                 // [d][q]
    float (*Kt)[65] = (float(*)[65])(smem + 64 * 65);       // [d][k]
    float (*Vs)[65] = (float(*)[65])(smem + 2 * 64 * 65);   // [k][d]
    float (*Ps)[64] = (float(*)[64])(smem + 3 * 64 * 65);   // [q][k]

    const int qb = blockIdx.x;          // 0..31 query block
    const int bh = blockIdx.y;          // 0..31
    const int b  = bh >> 4;
    const int h  = bh & 15;
    const int tid = threadIdx.x;
    const int ty = tid >> 4;            // q-tile index
    const int tx = tid & 15;            // k-tile / d-tile index

    const float* qbase = g_q + ((size_t)bh * Ss + (size_t)qb * 64) * DKk;
    const float* kbase = g_k + (size_t)bh * Ss * DKk;
    const float* vbase = g_v + (size_t)bh * Ss * DKk;

    // Load Q tile transposed
    for (int e = tid; e < 64 * 16; e += 256) {
        int r = e >> 4, c4 = (e & 15) * 4;
        float4 v = *(const float4*)(qbase + r * 64 + c4);
        Qt[c4 + 0][r] = v.x; Qt[c4 + 1][r] = v.y;
        Qt[c4 + 2][r] = v.z; Qt[c4 + 3][r] = v.w;
    }

    float m[4], l[4], O[4][4];
    #pragma unroll
    for (int i = 0; i < 4; i++) {
        m[i] = -INFINITY; l[i] = 0.f;
        #pragma unroll
        for (int j = 0; j < 4; j++) O[i][j] = 0.f;
    }

    for (int kb = 0; kb <= qb; kb++) {
        const float* kptr = kbase + (size_t)kb * 64 * DKk;
        const float* vptr = vbase + (size_t)kb * 64 * DKk;
        for (int e = tid; e < 64 * 16; e += 256) {
            int r = e >> 4, c4 = (e & 15) * 4;
            float4 kv = *(const float4*)(kptr + r * 64 + c4);
            Kt[c4 + 0][r] = kv.x; Kt[c4 + 1][r] = kv.y;
            Kt[c4 + 2][r] = kv.z; Kt[c4 + 3][r] = kv.w;
            float4 vv = *(const float4*)(vptr + r * 64 + c4);
            Vs[r][c4 + 0] = vv.x; Vs[r][c4 + 1] = vv.y;
            Vs[r][c4 + 2] = vv.z; Vs[r][c4 + 3] = vv.w;
        }
        __syncthreads();

        // scores 4x4
        float sc[4][4];
        #pragma unroll
        for (int i = 0; i < 4; i++)
            #pragma unroll
            for (int j = 0; j < 4; j++) sc[i][j] = 0.f;
        #pragma unroll 4
        for (int d = 0; d < 64; d++) {
            float a[4], bb[4];
            #pragma unroll
            for (int i = 0; i < 4; i++) a[i]  = Qt[d][ty * 4 + i];
            #pragma unroll
            for (int j = 0; j < 4; j++) bb[j] = Kt[d][tx * 4 + j];
            #pragma unroll
            for (int i = 0; i < 4; i++)
                #pragma unroll
                for (int j = 0; j < 4; j++)
                    sc[i][j] = fmaf(a[i], bb[j], sc[i][j]);
        }

        // scale + causal mask + online softmax update
        const float scale = 0.125f;   // 1/sqrt(64)
        #pragma unroll
        for (int i = 0; i < 4; i++) {
            const int qg = qb * 64 + ty * 4 + i;
            #pragma unroll
            for (int j = 0; j < 4; j++) {
                const int kg = kb * 64 + tx * 4 + j;
                sc[i][j] = (kg <= qg) ? sc[i][j] * scale : -1e30f;
            }
            float rmax = sc[i][0];
            #pragma unroll
            for (int j = 1; j < 4; j++) rmax = fmaxf(rmax, sc[i][j]);
            #pragma unroll
            for (int o = 1; o < 16; o <<= 1)
                rmax = fmaxf(rmax, __shfl_xor_sync(0xffffffffu, rmax, o));
            const float mnew  = fmaxf(m[i], rmax);
            const float alpha = expf(m[i] - mnew);
            float rs = 0.f;
            #pragma unroll
            for (int j = 0; j < 4; j++) {
                float pv = expf(sc[i][j] - mnew);
                Ps[ty * 4 + i][tx * 4 + j] = pv;
                rs += pv;
            }
            #pragma unroll
            for (int o = 1; o < 16; o <<= 1)
                rs += __shfl_xor_sync(0xffffffffu, rs, o);
            l[i] = l[i] * alpha + rs;
            m[i] = mnew;
            #pragma unroll
            for (int j = 0; j < 4; j++) O[i][j] *= alpha;
        }
        __syncthreads();

        // O += P @ V   (tx now indexes output dims)
        #pragma unroll 4
        for (int kk = 0; kk < 64; kk++) {
            float p[4], v[4];
            #pragma unroll
            for (int i = 0; i < 4; i++) p[i] = Ps[ty * 4 + i][kk];
            #pragma unroll
            for (int j = 0; j < 4; j++) v[j] = Vs[kk][tx * 4 + j];
            #pragma unroll
            for (int i = 0; i < 4; i++)
                #pragma unroll
                for (int j = 0; j < 4; j++)
                    O[i][j] = fmaf(p[i], v[j], O[i][j]);
        }
        __syncthreads();
    }

    // epilogue: normalize and write to [B,S,D] (D = h*64 + d)
    #pragma unroll
    for (int i = 0; i < 4; i++) {
        const int qg = qb * 64 + ty * 4 + i;
        const float invl = 1.0f / l[i];
        #pragma unroll
        for (int j = 0; j < 4; j++) {
            const int d = tx * 4 + j;
            g_att[((size_t)b * Ss + qg) * Dd + h * DKk + d] = O[i][j] * invl;
        }
    }
}

// ---------------------------------------------------------------------------
extern "C" void kernel_launch(void* const* d_in, const int* in_sizes, int n_in,
                              void* d_out, int out_size)
{
    const float* query = (const float*)d_in[0];
    const float* key   = (const float*)d_in[1];
    const float* value = (const float*)d_in[2];
    const float* Wq = (const float*)d_in[3];
    const float* bq = (const float*)d_in[4];
    const float* Wk = (const float*)d_in[5];
    const float* bk = (const float*)d_in[6];
    const float* Wv = (const float*)d_in[7];
    const float* bv = (const float*)d_in[8];
    const float* Wo = (const float*)d_in[9];
    const float* bo = (const float*)d_in[10];
    float* out = (float*)d_out;

    float *qp = nullptr, *kp = nullptr, *vp = nullptr, *attp = nullptr;
    cudaGetSymbolAddress((void**)&qp, g_q);
    cudaGetSymbolAddress((void**)&kp, g_k);
    cudaGetSymbolAddress((void**)&vp, g_v);
    cudaGetSymbolAddress((void**)&attp, g_att);

    dim3 ggrid(Dd / 64, (Bb * Ss) / 64);   // (16, 64)

    gemm_bias_kernel<<<ggrid, 256>>>(query, Wq, bq, qp, 1);
    gemm_bias_kernel<<<ggrid, 256>>>(key,   Wk, bk, kp, 1);
    gemm_bias_kernel<<<ggrid, 256>>>(value, Wv, bv, vp, 1);

    const int pairs = Bb * Hh * Ss * (DKk / 2);   // 2,097,152
    rope_kernel<<<(pairs + 255) / 256, 256>>>(qp, pairs);
    rope_kernel<<<(pairs + 255) / 256, 256>>>(kp, pairs);

    const size_t smem = (size_t)(3 * 64 * 65 + 64 * 64) * sizeof(float); // 66304 B
    cudaFuncSetAttribute(attn_kernel,
                         cudaFuncAttributeMaxDynamicSharedMemorySize, (int)smem);
    attn_kernel<<<dim3(Ss / 64, Bb * Hh), 256, smem>>>();

    gemm_bias_kernel<<<ggrid, 256>>>(attp, Wo, bo, out, 0);
}

// round 3
// speedup vs baseline: 1.4608x; 1.4608x over previous
#include <cuda_runtime.h>
#include <cuda_bf16.h>
#include <math.h>
#include <stdint.h>

#define Bb 2
#define Ss 2048
#define Dd 1024
#define Hh 16
#define DKk 64

// Scratch (device globals: allocation-free rule)
__device__ float g_q[(size_t)Bb * Hh * Ss * DKk];   // [B,H,S,DK]
__device__ float g_k[(size_t)Bb * Hh * Ss * DKk];
__device__ float g_v[(size_t)Bb * Hh * Ss * DKk];
__device__ float g_att[(size_t)Bb * Ss * Dd];       // [B,S,D]
__device__ float g_wt[4 * 1024 * 1024];             // 4 transposed weights

// ---------------------------------------------------------------------------
__device__ __forceinline__ uint32_t smem_u32(const void* p) {
    uint32_t a;
    asm("{ .reg .u64 t; cvta.to.shared.u64 t, %1; cvt.u32.u64 %0, t; }"
        : "=r"(a) : "l"(p));
    return a;
}

__device__ __forceinline__ void ldm_x4(uint32_t* r, uint32_t addr) {
    asm volatile("ldmatrix.sync.aligned.m8n8.x4.shared.b16 {%0,%1,%2,%3}, [%4];"
        : "=r"(r[0]), "=r"(r[1]), "=r"(r[2]), "=r"(r[3]) : "r"(addr));
}

__device__ __forceinline__ void mma_bf16(float* d, const uint32_t* a,
                                         const uint32_t* b) {
    asm volatile(
        "mma.sync.aligned.m16n8k16.row.col.f32.bf16.bf16.f32 "
        "{%0,%1,%2,%3}, {%4,%5,%6,%7}, {%8,%9}, {%0,%1,%2,%3};"
        : "+f"(d[0]), "+f"(d[1]), "+f"(d[2]), "+f"(d[3])
        : "r"(a[0]), "r"(a[1]), "r"(a[2]), "r"(a[3]), "r"(b[0]), "r"(b[1]));
}

// ---------------------------------------------------------------------------
// Weight transpose: Wt[n][k] = W[k][n], 1024x1024
// ---------------------------------------------------------------------------
__global__ void transpose_k(const float* __restrict__ W, float* __restrict__ Wt)
{
    __shared__ float t[32][33];
    const int bx = blockIdx.x * 32, by = blockIdx.y * 32;
    #pragma unroll
    for (int i = threadIdx.y; i < 32; i += 8)
        t[i][threadIdx.x] = W[(size_t)(by + i) * 1024 + bx + threadIdx.x];
    __syncthreads();
    #pragma unroll
    for (int i = threadIdx.y; i < 32; i += 8)
        Wt[(size_t)(bx + i) * 1024 + by + threadIdx.x] = t[threadIdx.x][i];
}

// ---------------------------------------------------------------------------
// Error-compensated bf16 mma.sync GEMM:
//   C = A[4096x1024] @ Bt^T + bias,  Bt row-major [N,K] (pre-transposed W).
// Split x = hi + lo (bf16 each); accumulate hh + hl + lh in fp32.
// CTA 128x128, 512 threads (16 warps m32n32), K-chunk 64.
// mode: bit0 = head-split [B,H,S,DK] output, bit1 = fuse RoPE.
// ---------------------------------------------------------------------------
#define GPAD 72   // bf16 columns per SMEM row (144 B stride)

__global__ __launch_bounds__(512, 1) void gemm_mma(
    const float* __restrict__ A, const float* __restrict__ Bt,
    const float* __restrict__ bias, float* __restrict__ C, int mode)
{
    extern __shared__ char sm[];
    __nv_bfloat16* Ah = (__nv_bfloat16*)sm;
    __nv_bfloat16* Al = Ah + 128 * GPAD;
    __nv_bfloat16* Bh = Al + 128 * GPAD;
    __nv_bfloat16* Bl = Bh + 128 * GPAD;
    __shared__ float sbias[128];

    const int tid = threadIdx.x;
    const int bm = blockIdx.y * 128;
    const int bn = blockIdx.x * 128;

    if (tid < 128) sbias[tid] = bias[bn + tid];

    const int lane = tid & 31;
    const int w = tid >> 5;        // 0..15
    const int wm = w & 3;          // m-tile of 32
    const int wn = w >> 2;         // n-tile of 32

    const uint32_t sAh = smem_u32(Ah), sAl = smem_u32(Al);
    const uint32_t sBh = smem_u32(Bh), sBl = smem_u32(Bl);

    float acc[2][4][4];
    #pragma unroll
    for (int mi = 0; mi < 2; mi++)
        #pragma unroll
        for (int ni = 0; ni < 4; ni++)
            #pragma unroll
            for (int q = 0; q < 4; q++) acc[mi][ni][q] = 0.f;

    // ldmatrix lane addressing (byte offsets within padded [128][GPAD] bf16)
    const int a_row_l = (lane & 15);
    const int a_col_l = ((lane & 16) >> 1);            // 0 or 8
    const int b_row_l = (lane & 7) + ((lane & 16) >> 1);
    const int b_col_l = (lane & 8);                    // 0 or 8

    for (int chunk = 0; chunk < 16; ++chunk) {
        const int k0 = chunk * 64;
        __syncthreads();   // previous chunk's MMAs done before overwrite

        // load + split-convert: 128 rows x 64 cols per matrix
        for (int e = tid; e < 2048; e += 512) {
            const int r = e >> 4;            // 0..127
            const int c = (e & 15) * 4;      // 0..60
            float4 x = *(const float4*)(A + (size_t)(bm + r) * 1024 + k0 + c);
            ushort4 hu, lu;
            __nv_bfloat16 h;
            h = __float2bfloat16_rn(x.x); hu.x = __bfloat16_as_ushort(h);
            lu.x = __bfloat16_as_ushort(__float2bfloat16_rn(x.x - __bfloat162float(h)));
            h = __float2bfloat16_rn(x.y); hu.y = __bfloat16_as_ushort(h);
            lu.y = __bfloat16_as_ushort(__float2bfloat16_rn(x.y - __bfloat162float(h)));
            h = __float2bfloat16_rn(x.z); hu.z = __bfloat16_as_ushort(h);
            lu.z = __bfloat16_as_ushort(__float2bfloat16_rn(x.z - __bfloat162float(h)));
            h = __float2bfloat16_rn(x.w); hu.w = __bfloat16_as_ushort(h);
            lu.w = __bfloat16_as_ushort(__float2bfloat16_rn(x.w - __bfloat162float(h)));
            *(ushort4*)(Ah + r * GPAD + c) = hu;
            *(ushort4*)(Al + r * GPAD + c) = lu;

            float4 y = *(const float4*)(Bt + (size_t)(bn + r) * 1024 + k0 + c);
            h = __float2bfloat16_rn(y.x); hu.x = __bfloat16_as_ushort(h);
            lu.x = __bfloat16_as_ushort(__float2bfloat16_rn(y.x - __bfloat162float(h)));
            h = __float2bfloat16_rn(y.y); hu.y = __bfloat16_as_ushort(h);
            lu.y = __bfloat16_as_ushort(__float2bfloat16_rn(y.y - __bfloat162float(h)));
            h = __float2bfloat16_rn(y.z); hu.z = __bfloat16_as_ushort(h);
            lu.z = __bfloat16_as_ushort(__float2bfloat16_rn(y.z - __bfloat162float(h)));
            h = __float2bfloat16_rn(y.w); hu.w = __bfloat16_as_ushort(h);
            lu.w = __bfloat16_as_ushort(__float2bfloat16_rn(y.w - __bfloat162float(h)));
            *(ushort4*)(Bh + r * GPAD + c) = hu;
            *(ushort4*)(Bl + r * GPAD + c) = lu;
        }
        __syncthreads();

        #pragma unroll
        for (int kk = 0; kk < 4; ++kk) {
            const int kc = kk * 16;
            uint32_t bh[4][2], bl[4][2];
            #pragma unroll
            for (int nt = 0; nt < 2; ++nt) {
                const int row = wn * 32 + nt * 16 + b_row_l;
                const int col = kc + b_col_l;
                uint32_t r4[4];
                ldm_x4(r4, sBh + (row * GPAD + col) * 2);
                bh[nt*2][0] = r4[0]; bh[nt*2][1] = r4[1];
                bh[nt*2+1][0] = r4[2]; bh[nt*2+1][1] = r4[3];
                ldm_x4(r4, sBl + (row * GPAD + col) * 2);
                bl[nt*2][0] = r4[0]; bl[nt*2][1] = r4[1];
                bl[nt*2+1][0] = r4[2]; bl[nt*2+1][1] = r4[3];
            }
            #pragma unroll
            for (int mi = 0; mi < 2; ++mi) {
                const int row = wm * 32 + mi * 16 + a_row_l;
                const int col = kc + a_col_l;
                uint32_t ah[4], al[4];
                ldm_x4(ah, sAh + (row * GPAD + col) * 2);
                ldm_x4(al, sAl + (row * GPAD + col) * 2);
                #pragma unroll
                for (int ni = 0; ni < 4; ++ni) {
                    mma_bf16(acc[mi][ni], ah, bh[ni]);
                    mma_bf16(acc[mi][ni], ah, bl[ni]);
                    mma_bf16(acc[mi][ni], al, bh[ni]);
                }
            }
        }
    }

    // ---------------- epilogue: bias (+rope) + store ----------------
    const int lr = lane >> 2;            // 0..7
    const int lc = (lane & 3) * 2;       // even col pair

    #pragma unroll
    for (int mi = 0; mi < 2; ++mi) {
        #pragma unroll
        for (int half = 0; half < 2; ++half) {
            const int m = bm + wm * 32 + mi * 16 + lr + half * 8;
            const int s_pos = m & (Ss - 1);
            const int b_idx = m >> 11;
            #pragma unroll
            for (int ni = 0; ni < 4; ++ni) {
                const int nl = wn * 32 + ni * 8 + lc;   // 0..127 within tile
                const int n = bn + nl;
                float f0 = acc[mi][ni][half * 2 + 0] + sbias[nl];
                float f1 = acc[mi][ni][half * 2 + 1] + sbias[nl + 1];

                if (mode & 2) {
                    const int d0 = n & 63;               // even
                    const int j0 = d0 & 31;
                    const int j1 = (d0 + 1) & 31;
                    const float inv0 = 1.0f / powf(10000.0f, (float)j0 * (1.0f / 32.0f));
                    const float inv1 = 1.0f / powf(10000.0f, (float)j1 * (1.0f / 32.0f));
                    float s0, c0, s1, c1;
                    sincosf((float)s_pos * inv0, &s0, &c0);
                    sincosf((float)s_pos * inv1, &s1, &c1);
                    const float x0 = f0, x1 = f1;
                    f0 = x0 * c0 - x1 * s1;
                    f1 = x0 * s0 + x1 * c1;
                }

                if (mode & 1) {
                    const int h = n >> 6, d = n & 63;
                    const size_t idx =
                        (((size_t)b_idx * Hh + h) * Ss + s_pos) * DKk + d;
                    *(float2*)(C + idx) = make_float2(f0, f1);
                } else {
                    *(float2*)(C + (size_t)m * Dd + n) = make_float2(f0, f1);
                }
            }
        }
    }
}

// ---------------------------------------------------------------------------
// Causal flash attention, fp32 (unchanged from validated round 1).
// ---------------------------------------------------------------------------
__global__ __launch_bounds__(256) void attn_kernel()
{
    extern __shared__ float smem[];
    float (*Qt)[65] = (float(*)[65])(smem);
    float (*Kt)[65] = (float(*)[65])(smem + 64 * 65);
    float (*Vs)[65] = (float(*)[65])(smem + 2 * 64 * 65);
    float (*Ps)[64] = (float(*)[64])(smem + 3 * 64 * 65);

    const int qb = blockIdx.x;
    const int bh = blockIdx.y;
    const int b  = bh >> 4;
    const int h  = bh & 15;
    const int tid = threadIdx.x;
    const int ty = tid >> 4;
    const int tx = tid & 15;

    const float* qbase = g_q + ((size_t)bh * Ss + (size_t)qb * 64) * DKk;
    const float* kbase = g_k + (size_t)bh * Ss * DKk;
    const float* vbase = g_v + (size_t)bh * Ss * DKk;

    for (int e = tid; e < 64 * 16; e += 256) {
        int r = e >> 4, c4 = (e & 15) * 4;
        float4 v = *(const float4*)(qbase + r * 64 + c4);
        Qt[c4 + 0][r] = v.x; Qt[c4 + 1][r] = v.y;
        Qt[c4 + 2][r] = v.z; Qt[c4 + 3][r] = v.w;
    }

    float m[4], l[4], O[4][4];
    #pragma unroll
    for (int i = 0; i < 4; i++) {
        m[i] = -INFINITY; l[i] = 0.f;
        #pragma unroll
        for (int j = 0; j < 4; j++) O[i][j] = 0.f;
    }

    for (int kb = 0; kb <= qb; kb++) {
        const float* kptr = kbase + (size_t)kb * 64 * DKk;
        const float* vptr = vbase + (size_t)kb * 64 * DKk;
        for (int e = tid; e < 64 * 16; e += 256) {
            int r = e >> 4, c4 = (e & 15) * 4;
            float4 kv = *(const float4*)(kptr + r * 64 + c4);
            Kt[c4 + 0][r] = kv.x; Kt[c4 + 1][r] = kv.y;
            Kt[c4 + 2][r] = kv.z; Kt[c4 + 3][r] = kv.w;
            float4 vv = *(const float4*)(vptr + r * 64 + c4);
            Vs[r][c4 + 0] = vv.x; Vs[r][c4 + 1] = vv.y;
            Vs[r][c4 + 2] = vv.z; Vs[r][c4 + 3] = vv.w;
        }
        __syncthreads();

        float sc[4][4];
        #pragma unroll
        for (int i = 0; i < 4; i++)
            #pragma unroll
            for (int j = 0; j < 4; j++) sc[i][j] = 0.f;
        #pragma unroll 4
        for (int d = 0; d < 64; d++) {
            float a[4], bb[4];
            #pragma unroll
            for (int i = 0; i < 4; i++) a[i]  = Qt[d][ty * 4 + i];
            #pragma unroll
            for (int j = 0; j < 4; j++) bb[j] = Kt[d][tx * 4 + j];
            #pragma unroll
            for (int i = 0; i < 4; i++)
                #pragma unroll
                for (int j = 0; j < 4; j++)
                    sc[i][j] = fmaf(a[i], bb[j], sc[i][j]);
        }

        const float scale = 0.125f;
        #pragma unroll
        for (int i = 0; i < 4; i++) {
            const int qg = qb * 64 + ty * 4 + i;
            #pragma unroll
            for (int j = 0; j < 4; j++) {
                const int kg = kb * 64 + tx * 4 + j;
                sc[i][j] = (kg <= qg) ? sc[i][j] * scale : -1e30f;
            }
            float rmax = sc[i][0];
            #pragma unroll
            for (int j = 1; j < 4; j++) rmax = fmaxf(rmax, sc[i][j]);
            #pragma unroll
            for (int o = 1; o < 16; o <<= 1)
                rmax = fmaxf(rmax, __shfl_xor_sync(0xffffffffu, rmax, o));
            const float mnew  = fmaxf(m[i], rmax);
            const float alpha = expf(m[i] - mnew);
            float rs = 0.f;
            #pragma unroll
            for (int j = 0; j < 4; j++) {
                float pv = expf(sc[i][j] - mnew);
                Ps[ty * 4 + i][tx * 4 + j] = pv;
                rs += pv;
            }
            #pragma unroll
            for (int o = 1; o < 16; o <<= 1)
                rs += __shfl_xor_sync(0xffffffffu, rs, o);
            l[i] = l[i] * alpha + rs;
            m[i] = mnew;
            #pragma unroll
            for (int j = 0; j < 4; j++) O[i][j] *= alpha;
        }
        __syncthreads();

        #pragma unroll 4
        for (int kk = 0; kk < 64; kk++) {
            float p[4], v[4];
            #pragma unroll
            for (int i = 0; i < 4; i++) p[i] = Ps[ty * 4 + i][kk];
            #pragma unroll
            for (int j = 0; j < 4; j++) v[j] = Vs[kk][tx * 4 + j];
            #pragma unroll
            for (int i = 0; i < 4; i++)
                #pragma unroll
                for (int j = 0; j < 4; j++)
                    O[i][j] = fmaf(p[i], v[j], O[i][j]);
        }
        __syncthreads();
    }

    #pragma unroll
    for (int i = 0; i < 4; i++) {
        const int qg = qb * 64 + ty * 4 + i;
        const float invl = 1.0f / l[i];
        #pragma unroll
        for (int j = 0; j < 4; j++) {
            const int d = tx * 4 + j;
            g_att[((size_t)b * Ss + qg) * Dd + h * DKk + d] = O[i][j] * invl;
        }
    }
}

// ---------------------------------------------------------------------------
extern "C" void kernel_launch(void* const* d_in, const int* in_sizes, int n_in,
                              void* d_out, int out_size)
{
    const float* query = (const float*)d_in[0];
    const float* key   = (const float*)d_in[1];
    const float* value = (const float*)d_in[2];
    const float* Wq = (const float*)d_in[3];
    const float* bq = (const float*)d_in[4];
    const float* Wk = (const float*)d_in[5];
    const float* bk = (const float*)d_in[6];
    const float* Wv = (const float*)d_in[7];
    const float* bv = (const float*)d_in[8];
    const float* Wo = (const float*)d_in[9];
    const float* bo = (const float*)d_in[10];
    float* out = (float*)d_out;

    float *qp = nullptr, *kp = nullptr, *vp = nullptr, *attp = nullptr, *wt = nullptr;
    cudaGetSymbolAddress((void**)&qp, g_q);
    cudaGetSymbolAddress((void**)&kp, g_k);
    cudaGetSymbolAddress((void**)&vp, g_v);
    cudaGetSymbolAddress((void**)&attp, g_att);
    cudaGetSymbolAddress((void**)&wt, g_wt);

    float* wtq = wt;
    float* wtk = wt + 1 * 1024 * 1024;
    float* wtv = wt + 2 * 1024 * 1024;
    float* wto = wt + 3 * 1024 * 1024;

    dim3 tgrid(32, 32), tblk(32, 8);
    transpose_k<<<tgrid, tblk>>>(Wq, wtq);
    transpose_k<<<tgrid, tblk>>>(Wk, wtk);
    transpose_k<<<tgrid, tblk>>>(Wv, wtv);
    transpose_k<<<tgrid, tblk>>>(Wo, wto);

    const int gsmem = 4 * 128 * GPAD * (int)sizeof(__nv_bfloat16);  // 73728
    cudaFuncSetAttribute(gemm_mma, cudaFuncAttributeMaxDynamicSharedMemorySize, gsmem);

    dim3 ggrid(Dd / 128, (Bb * Ss) / 128);    // (8, 32)
    gemm_mma<<<ggrid, 512, gsmem>>>(query, wtq, bq, qp, 3);   // head-split + rope
    gemm_mma<<<ggrid, 512, gsmem>>>(key,   wtk, bk, kp, 3);   // head-split + rope
    gemm_mma<<<ggrid, 512, gsmem>>>(value, wtv, bv, vp, 1);   // head-split

    const size_t asmem = (size_t)(3 * 64 * 65 + 64 * 64) * sizeof(float);
    cudaFuncSetAttribute(attn_kernel,
                         cudaFuncAttributeMaxDynamicSharedMemorySize, (int)asmem);
    attn_kernel<<<dim3(Ss / 64, Bb * Hh), 256, asmem>>>();

    gemm_mma<<<ggrid, 512, gsmem>>>(attp, wto, bo, out, 0);
}

// round 4
// speedup vs baseline: 2.1240x; 1.4541x over previous
#include <cuda_runtime.h>
#include <cuda_bf16.h>
#include <math.h>
#include <stdint.h>

#define Bb 2
#define Ss 2048
#define Dd 1024
#define Hh 16
#define DKk 64
#define GPAD 72   // bf16 columns per SMEM row (144 B stride, ldmatrix conflict-free)

// Scratch (device globals: allocation-free rule)
__device__ float g_q[(size_t)Bb * Hh * Ss * DKk];   // [B,H,S,DK]
__device__ float g_k[(size_t)Bb * Hh * Ss * DKk];
__device__ float g_v[(size_t)Bb * Hh * Ss * DKk];
__device__ float g_att[(size_t)Bb * Ss * Dd];       // [B,S,D]
__device__ float g_wt[4 * 1024 * 1024];             // 4 transposed weights

// ---------------------------------------------------------------------------
__device__ __forceinline__ uint32_t smem_u32(const void* p) {
    uint32_t a;
    asm("{ .reg .u64 t; cvta.to.shared.u64 t, %1; cvt.u32.u64 %0, t; }"
        : "=r"(a) : "l"(p));
    return a;
}

__device__ __forceinline__ void ldm_x4(uint32_t* r, uint32_t addr) {
    asm volatile("ldmatrix.sync.aligned.m8n8.x4.shared.b16 {%0,%1,%2,%3}, [%4];"
        : "=r"(r[0]), "=r"(r[1]), "=r"(r[2]), "=r"(r[3]) : "r"(addr));
}

__device__ __forceinline__ void ldm_x4_t(uint32_t* r, uint32_t addr) {
    asm volatile("ldmatrix.sync.aligned.m8n8.x4.trans.shared.b16 {%0,%1,%2,%3}, [%4];"
        : "=r"(r[0]), "=r"(r[1]), "=r"(r[2]), "=r"(r[3]) : "r"(addr));
}

__device__ __forceinline__ void mma_bf16(float* d, const uint32_t* a,
                                         const uint32_t* b) {
    asm volatile(
        "mma.sync.aligned.m16n8k16.row.col.f32.bf16.bf16.f32 "
        "{%0,%1,%2,%3}, {%4,%5,%6,%7}, {%8,%9}, {%0,%1,%2,%3};"
        : "+f"(d[0]), "+f"(d[1]), "+f"(d[2]), "+f"(d[3])
        : "r"(a[0]), "r"(a[1]), "r"(a[2]), "r"(a[3]), "r"(b[0]), "r"(b[1]));
}

__device__ __forceinline__ uint32_t pack2(__nv_bfloat16 a, __nv_bfloat16 b) {
    return (uint32_t)__bfloat16_as_ushort(a) |
           ((uint32_t)__bfloat16_as_ushort(b) << 16);
}

// split a float4 into hi/lo bf16 quads and store
__device__ __forceinline__ void split4(float4 x, __nv_bfloat16* hp,
                                       __nv_bfloat16* lp) {
    ushort4 hu, lu;
    __nv_bfloat16 h;
    h = __float2bfloat16_rn(x.x); hu.x = __bfloat16_as_ushort(h);
    lu.x = __bfloat16_as_ushort(__float2bfloat16_rn(x.x - __bfloat162float(h)));
    h = __float2bfloat16_rn(x.y); hu.y = __bfloat16_as_ushort(h);
    lu.y = __bfloat16_as_ushort(__float2bfloat16_rn(x.y - __bfloat162float(h)));
    h = __float2bfloat16_rn(x.z); hu.z = __bfloat16_as_ushort(h);
    lu.z = __bfloat16_as_ushort(__float2bfloat16_rn(x.z - __bfloat162float(h)));
    h = __float2bfloat16_rn(x.w); hu.w = __bfloat16_as_ushort(h);
    lu.w = __bfloat16_as_ushort(__float2bfloat16_rn(x.w - __bfloat162float(h)));
    *(ushort4*)hp = hu;
    *(ushort4*)lp = lu;
}

// ---------------------------------------------------------------------------
// Weight transpose: Wt[n][k] = W[k][n], 1024x1024
// ---------------------------------------------------------------------------
__global__ void transpose_k(const float* __restrict__ W, float* __restrict__ Wt)
{
    __shared__ float t[32][33];
    const int bx = blockIdx.x * 32, by = blockIdx.y * 32;
    #pragma unroll
    for (int i = threadIdx.y; i < 32; i += 8)
        t[i][threadIdx.x] = W[(size_t)(by + i) * 1024 + bx + threadIdx.x];
    __syncthreads();
    #pragma unroll
    for (int i = threadIdx.y; i < 32; i += 8)
        Wt[(size_t)(bx + i) * 1024 + by + threadIdx.x] = t[threadIdx.x][i];
}

// ---------------------------------------------------------------------------
// Error-compensated bf16 mma.sync GEMM (validated R3):
//   C = A[4096x1024] @ Bt^T + bias,  Bt row-major [N,K].
// mode: bit0 = head-split [B,H,S,DK] output, bit1 = fuse RoPE.
// ---------------------------------------------------------------------------
__global__ __launch_bounds__(512, 1) void gemm_mma(
    const float* __restrict__ A, const float* __restrict__ Bt,
    const float* __restrict__ bias, float* __restrict__ C, int mode)
{
    extern __shared__ char sm[];
    __nv_bfloat16* Ah = (__nv_bfloat16*)sm;
    __nv_bfloat16* Al = Ah + 128 * GPAD;
    __nv_bfloat16* Bh = Al + 128 * GPAD;
    __nv_bfloat16* Bl = Bh + 128 * GPAD;
    __shared__ float sbias[128];

    const int tid = threadIdx.x;
    const int bm = blockIdx.y * 128;
    const int bn = blockIdx.x * 128;

    if (tid < 128) sbias[tid] = bias[bn + tid];

    const int lane = tid & 31;
    const int w = tid >> 5;
    const int wm = w & 3;
    const int wn = w >> 2;

    const uint32_t sAh = smem_u32(Ah), sAl = smem_u32(Al);
    const uint32_t sBh = smem_u32(Bh), sBl = smem_u32(Bl);

    float acc[2][4][4];
    #pragma unroll
    for (int mi = 0; mi < 2; mi++)
        #pragma unroll
        for (int ni = 0; ni < 4; ni++)
            #pragma unroll
            for (int q = 0; q < 4; q++) acc[mi][ni][q] = 0.f;

    const int a_row_l = (lane & 15);
    const int a_col_l = ((lane & 16) >> 1);
    const int b_row_l = (lane & 7) + ((lane & 16) >> 1);
    const int b_col_l = (lane & 8);

    for (int chunk = 0; chunk < 16; ++chunk) {
        const int k0 = chunk * 64;
        __syncthreads();

        for (int e = tid; e < 2048; e += 512) {
            const int r = e >> 4;
            const int c = (e & 15) * 4;
            float4 x = *(const float4*)(A + (size_t)(bm + r) * 1024 + k0 + c);
            split4(x, Ah + r * GPAD + c, Al + r * GPAD + c);
            float4 y = *(const float4*)(Bt + (size_t)(bn + r) * 1024 + k0 + c);
            split4(y, Bh + r * GPAD + c, Bl + r * GPAD + c);
        }
        __syncthreads();

        #pragma unroll
        for (int kk = 0; kk < 4; ++kk) {
            const int kc = kk * 16;
            uint32_t bh[4][2], bl[4][2];
            #pragma unroll
            for (int nt = 0; nt < 2; ++nt) {
                const int row = wn * 32 + nt * 16 + b_row_l;
                const int col = kc + b_col_l;
                uint32_t r4[4];
                ldm_x4(r4, sBh + (row * GPAD + col) * 2);
                bh[nt*2][0] = r4[0]; bh[nt*2][1] = r4[1];
                bh[nt*2+1][0] = r4[2]; bh[nt*2+1][1] = r4[3];
                ldm_x4(r4, sBl + (row * GPAD + col) * 2);
                bl[nt*2][0] = r4[0]; bl[nt*2][1] = r4[1];
                bl[nt*2+1][0] = r4[2]; bl[nt*2+1][1] = r4[3];
            }
            #pragma unroll
            for (int mi = 0; mi < 2; ++mi) {
                const int row = wm * 32 + mi * 16 + a_row_l;
                const int col = kc + a_col_l;
                uint32_t ah[4], al[4];
                ldm_x4(ah, sAh + (row * GPAD + col) * 2);
                ldm_x4(al, sAl + (row * GPAD + col) * 2);
                #pragma unroll
                for (int ni = 0; ni < 4; ++ni) {
                    mma_bf16(acc[mi][ni], ah, bh[ni]);
                    mma_bf16(acc[mi][ni], ah, bl[ni]);
                    mma_bf16(acc[mi][ni], al, bh[ni]);
                }
            }
        }
    }

    const int lr = lane >> 2;
    const int lc = (lane & 3) * 2;

    #pragma unroll
    for (int mi = 0; mi < 2; ++mi) {
        #pragma unroll
        for (int half = 0; half < 2; ++half) {
            const int m = bm + wm * 32 + mi * 16 + lr + half * 8;
            const int s_pos = m & (Ss - 1);
            const int b_idx = m >> 11;
            #pragma unroll
            for (int ni = 0; ni < 4; ++ni) {
                const int nl = wn * 32 + ni * 8 + lc;
                const int n = bn + nl;
                float f0 = acc[mi][ni][half * 2 + 0] + sbias[nl];
                float f1 = acc[mi][ni][half * 2 + 1] + sbias[nl + 1];

                if (mode & 2) {
                    const int d0 = n & 63;
                    const int j0 = d0 & 31;
                    const int j1 = (d0 + 1) & 31;
                    const float inv0 = 1.0f / powf(10000.0f, (float)j0 * (1.0f / 32.0f));
                    const float inv1 = 1.0f / powf(10000.0f, (float)j1 * (1.0f / 32.0f));
                    float s0, c0, s1, c1;
                    sincosf((float)s_pos * inv0, &s0, &c0);
                    sincosf((float)s_pos * inv1, &s1, &c1);
                    const float x0 = f0, x1 = f1;
                    f0 = x0 * c0 - x1 * s1;
                    f1 = x0 * s0 + x1 * c1;
                }

                if (mode & 1) {
                    const int h = n >> 6, d = n & 63;
                    const size_t idx =
                        (((size_t)b_idx * Hh + h) * Ss + s_pos) * DKk + d;
                    *(float2*)(C + idx) = make_float2(f0, f1);
                } else {
                    *(float2*)(C + (size_t)m * Dd + n) = make_float2(f0, f1);
                }
            }
        }
    }
}

// ---------------------------------------------------------------------------
// Causal flash attention with error-compensated bf16 mma.sync.
// CTA = 128 queries of one (b,h); 8 warps x 16 query rows; 64-key blocks.
// ---------------------------------------------------------------------------
__global__ __launch_bounds__(256, 1) void attn_mma()
{
    extern __shared__ __nv_bfloat16 smb[];
    __nv_bfloat16* Qh = smb;
    __nv_bfloat16* Ql = Qh + 128 * GPAD;
    __nv_bfloat16* Kh = Ql + 128 * GPAD;
    __nv_bfloat16* Kl = Kh + 64 * GPAD;
    __nv_bfloat16* Vh = Kl + 64 * GPAD;
    __nv_bfloat16* Vl = Vh + 64 * GPAD;

    const int qb = gridDim.x - 1 - blockIdx.x;   // heavy blocks first
    const int bh = blockIdx.y;
    const int bidx = bh >> 4;
    const int head = bh & 15;
    const int tid = threadIdx.x;
    const int lane = tid & 31;
    const int w = tid >> 5;
    const int wq = w * 16;

    const float* qg = g_q + ((size_t)bh * Ss + (size_t)qb * 128) * DKk;
    const float* kg = g_k + (size_t)bh * Ss * DKk;
    const float* vg = g_v + (size_t)bh * Ss * DKk;

    // fill Q (128 x 64) split hi/lo
    for (int e = tid; e < 128 * 16; e += 256) {
        const int r = e >> 4, c = (e & 15) * 4;
        float4 x = *(const float4*)(qg + r * 64 + c);
        split4(x, Qh + r * GPAD + c, Ql + r * GPAD + c);
    }
    __syncthreads();

    const uint32_t sQh = smem_u32(Qh), sQl = smem_u32(Ql);
    const uint32_t sKh = smem_u32(Kh), sKl = smem_u32(Kl);
    const uint32_t sVh = smem_u32(Vh), sVl = smem_u32(Vl);

    const int a_row = lane & 15;
    const int a_col = (lane & 16) >> 1;
    const int b_row = (lane & 7) + ((lane & 16) >> 1);
    const int b_col = lane & 8;
    const int v_key = ((lane >> 3) & 1) * 8 + (lane & 7);   // trans addressing
    const int v_dim = (lane >> 4) * 8;

    // Q fragments (held in registers for the whole CTA lifetime)
    uint32_t qfh[4][4], qfl[4][4];
    #pragma unroll
    for (int kt = 0; kt < 4; ++kt) {
        const uint32_t off = ((wq + a_row) * GPAD + kt * 16 + a_col) * 2;
        ldm_x4(qfh[kt], sQh + off);
        ldm_x4(qfl[kt], sQl + off);
    }

    float O[8][4];
    #pragma unroll
    for (int nf = 0; nf < 8; ++nf)
        #pragma unroll
        for (int j = 0; j < 4; ++j) O[nf][j] = 0.f;
    float mrow[2] = {-INFINITY, -INFINITY};
    float lrow[2] = {0.f, 0.f};

    const int lr = lane >> 2;
    const int lc2 = (lane & 3) * 2;
    const int q0 = qb * 128 + wq + lr;       // + 8*half for the second row
    const int warp_qmax = qb * 128 + wq + 15;
    const int nkb = 2 * qb + 2;

    for (int kb = 0; kb < nkb; ++kb) {
        __syncthreads();   // protect previous iteration's SMEM use
        const float* kp = kg + (size_t)kb * 64 * DKk;
        const float* vp = vg + (size_t)kb * 64 * DKk;
        for (int e = tid; e < 64 * 16; e += 256) {
            const int r = e >> 4, c = (e & 15) * 4;
            float4 kx = *(const float4*)(kp + r * 64 + c);
            split4(kx, Kh + r * GPAD + c, Kl + r * GPAD + c);
            float4 vx = *(const float4*)(vp + r * 64 + c);
            split4(vx, Vh + r * GPAD + c, Vl + r * GPAD + c);
        }
        __syncthreads();

        if (kb * 64 > warp_qmax) continue;   // fully masked for this warp

        // ---- scores = Q K^T (hh + hl + lh) ----
        float acc[8][4];
        #pragma unroll
        for (int nf = 0; nf < 8; ++nf)
            #pragma unroll
            for (int j = 0; j < 4; ++j) acc[nf][j] = 0.f;

        #pragma unroll
        for (int kt = 0; kt < 4; ++kt) {
            const int kc = kt * 16;
            #pragma unroll
            for (int ntp = 0; ntp < 4; ++ntp) {
                uint32_t rh[4], rl[4];
                const uint32_t off = ((ntp * 16 + b_row) * GPAD + kc + b_col) * 2;
                ldm_x4(rh, sKh + off);
                ldm_x4(rl, sKl + off);
                uint32_t b0h[2] = {rh[0], rh[1]}, b1h[2] = {rh[2], rh[3]};
                uint32_t b0l[2] = {rl[0], rl[1]}, b1l[2] = {rl[2], rl[3]};
                mma_bf16(acc[2*ntp],   qfh[kt], b0h);
                mma_bf16(acc[2*ntp],   qfh[kt], b0l);
                mma_bf16(acc[2*ntp],   qfl[kt], b0h);
                mma_bf16(acc[2*ntp+1], qfh[kt], b1h);
                mma_bf16(acc[2*ntp+1], qfh[kt], b1l);
                mma_bf16(acc[2*ntp+1], qfl[kt], b1h);
            }
        }

        // ---- scale + causal mask ----
        const bool diag = (kb >= 2 * qb);
        #pragma unroll
        for (int nf = 0; nf < 8; ++nf) {
            #pragma unroll
            for (int j = 0; j < 4; ++j) {
                const float v = acc[nf][j] * 0.125f;
                if (diag) {
                    const int kgl = kb * 64 + nf * 8 + lc2 + (j & 1);
                    const int qgl = q0 + 8 * (j >> 1);
                    acc[nf][j] = (kgl <= qgl) ? v : -1e30f;
                } else {
                    acc[nf][j] = v;
                }
            }
        }

        // ---- online softmax (per row-half) ----
        #pragma unroll
        for (int half = 0; half < 2; ++half) {
            float rm = -1e30f;
            #pragma unroll
            for (int nf = 0; nf < 8; ++nf)
                rm = fmaxf(rm, fmaxf(acc[nf][2*half], acc[nf][2*half+1]));
            rm = fmaxf(rm, __shfl_xor_sync(0xffffffffu, rm, 1));
            rm = fmaxf(rm, __shfl_xor_sync(0xffffffffu, rm, 2));
            const float mn = fmaxf(mrow[half], rm);
            const float alpha = __expf(mrow[half] - mn);
            mrow[half] = mn;
            float rs = 0.f;
            #pragma unroll
            for (int nf = 0; nf < 8; ++nf) {
                const float p0 = __expf(acc[nf][2*half]   - mn);
                const float p1 = __expf(acc[nf][2*half+1] - mn);
                acc[nf][2*half]   = p0;
                acc[nf][2*half+1] = p1;
                rs += p0 + p1;
            }
            rs += __shfl_xor_sync(0xffffffffu, rs, 1);
            rs += __shfl_xor_sync(0xffffffffu, rs, 2);
            lrow[half] = lrow[half] * alpha + rs;
            #pragma unroll
            for (int nf = 0; nf < 8; ++nf) {
                O[nf][2*half]   *= alpha;
                O[nf][2*half+1] *= alpha;
            }
        }

        // ---- O += P V (hh + hl + lh), P packed from acc in-register ----
        #pragma unroll
        for (int kt = 0; kt < 4; ++kt) {
            uint32_t ah[4], al[4];
            #pragma unroll
            for (int f = 0; f < 4; ++f) {
                const float p0 = acc[2*kt + (f >> 1)][(f & 1) * 2 + 0];
                const float p1 = acc[2*kt + (f >> 1)][(f & 1) * 2 + 1];
                const __nv_bfloat16 h0 = __float2bfloat16_rn(p0);
                const __nv_bfloat16 h1 = __float2bfloat16_rn(p1);
                ah[f] = pack2(h0, h1);
                al[f] = pack2(__float2bfloat16_rn(p0 - __bfloat162float(h0)),
                              __float2bfloat16_rn(p1 - __bfloat162float(h1)));
            }
            #pragma unroll
            for (int nd = 0; nd < 4; ++nd) {
                uint32_t vh4[4], vl4[4];
                const uint32_t off = ((kt * 16 + v_key) * GPAD + nd * 16 + v_dim) * 2;
                ldm_x4_t(vh4, sVh + off);
                ldm_x4_t(vl4, sVl + off);
                uint32_t b0h[2] = {vh4[0], vh4[1]}, b1h[2] = {vh4[2], vh4[3]};
                uint32_t b0l[2] = {vl4[0], vl4[1]}, b1l[2] = {vl4[2], vl4[3]};
                mma_bf16(O[2*nd],   ah, b0h);
                mma_bf16(O[2*nd],   ah, b0l);
                mma_bf16(O[2*nd],   al, b0h);
                mma_bf16(O[2*nd+1], ah, b1h);
                mma_bf16(O[2*nd+1], ah, b1l);
                mma_bf16(O[2*nd+1], al, b1h);
            }
        }
    }

    // ---- normalize + store to g_att[B,S,D] ----
    #pragma unroll
    for (int half = 0; half < 2; ++half) {
        const int qgl = q0 + 8 * half;
        const float inv = 1.0f / lrow[half];
        float* outp = g_att + ((size_t)bidx * Ss + qgl) * Dd + head * 64;
        #pragma unroll
        for (int nf = 0; nf < 8; ++nf) {
            *(float2*)(outp + nf * 8 + lc2) =
                make_float2(O[nf][2*half] * inv, O[nf][2*half+1] * inv);
        }
    }
}

// ---------------------------------------------------------------------------
extern "C" void kernel_launch(void* const* d_in, const int* in_sizes, int n_in,
                              void* d_out, int out_size)
{
    const float* query = (const float*)d_in[0];
    const float* key   = (const float*)d_in[1];
    const float* value = (const float*)d_in[2];
    const float* Wq = (const float*)d_in[3];
    const float* bq = (const float*)d_in[4];
    const float* Wk = (const float*)d_in[5];
    const float* bk = (const float*)d_in[6];
    const float* Wv = (const float*)d_in[7];
    const float* bv = (const float*)d_in[8];
    const float* Wo = (const float*)d_in[9];
    const float* bo = (const float*)d_in[10];
    float* out = (float*)d_out;

    float *qp = nullptr, *kp = nullptr, *vp = nullptr, *attp = nullptr, *wt = nullptr;
    cudaGetSymbolAddress((void**)&qp, g_q);
    cudaGetSymbolAddress((void**)&kp, g_k);
    cudaGetSymbolAddress((void**)&vp, g_v);
    cudaGetSymbolAddress((void**)&attp, g_att);
    cudaGetSymbolAddress((void**)&wt, g_wt);

    float* wtq = wt;
    float* wtk = wt + 1 * 1024 * 1024;
    float* wtv = wt + 2 * 1024 * 1024;
    float* wto = wt + 3 * 1024 * 1024;

    dim3 tgrid(32, 32), tblk(32, 8);
    transpose_k<<<tgrid, tblk>>>(Wq, wtq);
    transpose_k<<<tgrid, tblk>>>(Wk, wtk);
    transpose_k<<<tgrid, tblk>>>(Wv, wtv);
    transpose_k<<<tgrid, tblk>>>(Wo, wto);

    const int gsmem = 4 * 128 * GPAD * (int)sizeof(__nv_bfloat16);  // 73728
    cudaFuncSetAttribute(gemm_mma, cudaFuncAttributeMaxDynamicSharedMemorySize, gsmem);

    dim3 ggrid(Dd / 128, (Bb * Ss) / 128);    // (8, 32)
    gemm_mma<<<ggrid, 512, gsmem>>>(query, wtq, bq, qp, 3);   // head-split + rope
    gemm_mma<<<ggrid, 512, gsmem>>>(key,   wtk, bk, kp, 3);   // head-split + rope
    gemm_mma<<<ggrid, 512, gsmem>>>(value, wtv, bv, vp, 1);   // head-split

    const int asmem = (2 * 128 + 4 * 64) * GPAD * (int)sizeof(__nv_bfloat16); // 73728
    cudaFuncSetAttribute(attn_mma, cudaFuncAttributeMaxDynamicSharedMemorySize, asmem);
    attn_mma<<<dim3(Ss / 128, Bb * Hh), 256, asmem>>>();

    gemm_mma<<<ggrid, 512, gsmem>>>(attp, wto, bo, out, 0);
}

// round 5
// speedup vs baseline: 3.1442x; 1.4803x over previous
#include <cuda_runtime.h>
#include <cuda_bf16.h>
#include <math.h>
#include <stdint.h>

#define Bb 2
#define Ss 2048
#define Dd 1024
#define Hh 16
#define DKk 64
#define GPAD 72   // bf16 columns per SMEM row (144 B stride, ldmatrix conflict-free)

// Scratch (device globals: allocation-free rule). All pre-split bf16 hi/lo.
#define QKV_ELEMS ((size_t)Bb * Hh * Ss * DKk)
__device__ __nv_bfloat16 g_qh[QKV_ELEMS], g_ql[QKV_ELEMS];
__device__ __nv_bfloat16 g_kh[QKV_ELEMS], g_kl[QKV_ELEMS];
__device__ __nv_bfloat16 g_vh[QKV_ELEMS], g_vl[QKV_ELEMS];
__device__ __nv_bfloat16 g_ath[(size_t)Bb * Ss * Dd], g_atl[(size_t)Bb * Ss * Dd];
__device__ __nv_bfloat16 g_wth[4 * 1024 * 1024], g_wtl[4 * 1024 * 1024];

// ---------------------------------------------------------------------------
__device__ __forceinline__ uint32_t smem_u32(const void* p) {
    uint32_t a;
    asm("{ .reg .u64 t; cvta.to.shared.u64 t, %1; cvt.u32.u64 %0, t; }"
        : "=r"(a) : "l"(p));
    return a;
}

__device__ __forceinline__ void ldm_x4(uint32_t* r, uint32_t addr) {
    asm volatile("ldmatrix.sync.aligned.m8n8.x4.shared.b16 {%0,%1,%2,%3}, [%4];"
        : "=r"(r[0]), "=r"(r[1]), "=r"(r[2]), "=r"(r[3]) : "r"(addr));
}

__device__ __forceinline__ void ldm_x4_t(uint32_t* r, uint32_t addr) {
    asm volatile("ldmatrix.sync.aligned.m8n8.x4.trans.shared.b16 {%0,%1,%2,%3}, [%4];"
        : "=r"(r[0]), "=r"(r[1]), "=r"(r[2]), "=r"(r[3]) : "r"(addr));
}

__device__ __forceinline__ void mma_bf16(float* d, const uint32_t* a,
                                         const uint32_t* b) {
    asm volatile(
        "mma.sync.aligned.m16n8k16.row.col.f32.bf16.bf16.f32 "
        "{%0,%1,%2,%3}, {%4,%5,%6,%7}, {%8,%9}, {%0,%1,%2,%3};"
        : "+f"(d[0]), "+f"(d[1]), "+f"(d[2]), "+f"(d[3])
        : "r"(a[0]), "r"(a[1]), "r"(a[2]), "r"(a[3]), "r"(b[0]), "r"(b[1]));
}

#define CP16(dst, src) \
    asm volatile("cp.async.ca.shared.global [%0], [%1], 16;" \
        :: "r"((uint32_t)(dst)), "l"(src) : "memory")
#define CP_COMMIT() asm volatile("cp.async.commit_group;" ::: "memory")
#define CP_WAIT0()  asm volatile("cp.async.wait_group 0;" ::: "memory")

__device__ __forceinline__ uint32_t pack2(__nv_bfloat16 a, __nv_bfloat16 b) {
    return (uint32_t)__bfloat16_as_ushort(a) |
           ((uint32_t)__bfloat16_as_ushort(b) << 16);
}

// split a float4 into hi/lo bf16 quads and store
__device__ __forceinline__ void split4(float4 x, __nv_bfloat16* hp,
                                       __nv_bfloat16* lp) {
    ushort4 hu, lu;
    __nv_bfloat16 h;
    h = __float2bfloat16_rn(x.x); hu.x = __bfloat16_as_ushort(h);
    lu.x = __bfloat16_as_ushort(__float2bfloat16_rn(x.x - __bfloat162float(h)));
    h = __float2bfloat16_rn(x.y); hu.y = __bfloat16_as_ushort(h);
    lu.y = __bfloat16_as_ushort(__float2bfloat16_rn(x.y - __bfloat162float(h)));
    h = __float2bfloat16_rn(x.z); hu.z = __bfloat16_as_ushort(h);
    lu.z = __bfloat16_as_ushort(__float2bfloat16_rn(x.z - __bfloat162float(h)));
    h = __float2bfloat16_rn(x.w); hu.w = __bfloat16_as_ushort(h);
    lu.w = __bfloat16_as_ushort(__float2bfloat16_rn(x.w - __bfloat162float(h)));
    *(ushort4*)hp = hu;
    *(ushort4*)lp = lu;
}

// ---------------------------------------------------------------------------
// Weight transpose + hi/lo split: Wth/Wtl[n][k] = split(W[k][n])
// ---------------------------------------------------------------------------
__global__ void transpose_split(const float* __restrict__ W,
                                __nv_bfloat16* __restrict__ Wth,
                                __nv_bfloat16* __restrict__ Wtl)
{
    __shared__ float t[32][33];
    const int bx = blockIdx.x * 32, by = blockIdx.y * 32;
    #pragma unroll
    for (int i = threadIdx.y; i < 32; i += 8)
        t[i][threadIdx.x] = W[(size_t)(by + i) * 1024 + bx + threadIdx.x];
    __syncthreads();
    #pragma unroll
    for (int i = threadIdx.y; i < 32; i += 8) {
        const float v = t[threadIdx.x][i];
        const __nv_bfloat16 h = __float2bfloat16_rn(v);
        const size_t idx = (size_t)(bx + i) * 1024 + by + threadIdx.x;
        Wth[idx] = h;
        Wtl[idx] = __float2bfloat16_rn(v - __bfloat162float(h));
    }
}

// ---------------------------------------------------------------------------
// Error-compensated bf16 mma.sync GEMM.
//   A fp32 [M,K] (or pre-split Ahg/Alg if mode&4); B pre-split [N,K].
// mode: bit0 = head-split bf16 hi/lo output (+bias), bit1 = fuse RoPE,
//       bit2 = A pre-split.  bit0 clear = fp32 row-major output to Cf.
// ---------------------------------------------------------------------------
__global__ __launch_bounds__(512, 1) void gemm_mma(
    const float* __restrict__ A,
    const __nv_bfloat16* __restrict__ Ahg, const __nv_bfloat16* __restrict__ Alg,
    const __nv_bfloat16* __restrict__ Bth, const __nv_bfloat16* __restrict__ Btl,
    const float* __restrict__ bias, float* __restrict__ Cf,
    __nv_bfloat16* __restrict__ Ch, __nv_bfloat16* __restrict__ Cl, int mode)
{
    extern __shared__ char sm[];
    __nv_bfloat16* Ah = (__nv_bfloat16*)sm;
    __nv_bfloat16* Al = Ah + 128 * GPAD;
    __nv_bfloat16* Bh = Al + 128 * GPAD;
    __nv_bfloat16* Bl = Bh + 128 * GPAD;
    __shared__ float sbias[128];

    const int tid = threadIdx.x;
    const int bm = blockIdx.y * 128;
    const int bn = blockIdx.x * 128;

    if (tid < 128) sbias[tid] = bias[bn + tid];

    const int lane = tid & 31;
    const int w = tid >> 5;
    const int wm = w & 3;
    const int wn = w >> 2;

    const uint32_t sAh = smem_u32(Ah), sAl = smem_u32(Al);
    const uint32_t sBh = smem_u32(Bh), sBl = smem_u32(Bl);

    float acc[2][4][4];
    #pragma unroll
    for (int mi = 0; mi < 2; mi++)
        #pragma unroll
        for (int ni = 0; ni < 4; ni++)
            #pragma unroll
            for (int q = 0; q < 4; q++) acc[mi][ni][q] = 0.f;

    const int a_row_l = (lane & 15);
    const int a_col_l = ((lane & 16) >> 1);
    const int b_row_l = (lane & 7) + ((lane & 16) >> 1);
    const int b_col_l = (lane & 8);

    for (int chunk = 0; chunk < 16; ++chunk) {
        const int k0 = chunk * 64;
        __syncthreads();

        if (mode & 4) {
            #pragma unroll
            for (int e = tid; e < 1024; e += 512) {
                const int r = e >> 3, c = (e & 7) * 8;
                *(uint4*)(Ah + r * GPAD + c) =
                    *(const uint4*)(Ahg + (size_t)(bm + r) * 1024 + k0 + c);
                *(uint4*)(Al + r * GPAD + c) =
                    *(const uint4*)(Alg + (size_t)(bm + r) * 1024 + k0 + c);
            }
        } else {
            #pragma unroll
            for (int e = tid; e < 2048; e += 512) {
                const int r = e >> 4, c = (e & 15) * 4;
                float4 x = *(const float4*)(A + (size_t)(bm + r) * 1024 + k0 + c);
                split4(x, Ah + r * GPAD + c, Al + r * GPAD + c);
            }
        }
        #pragma unroll
        for (int e = tid; e < 1024; e += 512) {
            const int r = e >> 3, c = (e & 7) * 8;
            *(uint4*)(Bh + r * GPAD + c) =
                *(const uint4*)(Bth + (size_t)(bn + r) * 1024 + k0 + c);
            *(uint4*)(Bl + r * GPAD + c) =
                *(const uint4*)(Btl + (size_t)(bn + r) * 1024 + k0 + c);
        }
        __syncthreads();

        #pragma unroll
        for (int kk = 0; kk < 4; ++kk) {
            const int kc = kk * 16;
            uint32_t bh[4][2], bl[4][2];
            #pragma unroll
            for (int nt = 0; nt < 2; ++nt) {
                const int row = wn * 32 + nt * 16 + b_row_l;
                const int col = kc + b_col_l;
                uint32_t r4[4];
                ldm_x4(r4, sBh + (row * GPAD + col) * 2);
                bh[nt*2][0] = r4[0]; bh[nt*2][1] = r4[1];
                bh[nt*2+1][0] = r4[2]; bh[nt*2+1][1] = r4[3];
                ldm_x4(r4, sBl + (row * GPAD + col) * 2);
                bl[nt*2][0] = r4[0]; bl[nt*2][1] = r4[1];
                bl[nt*2+1][0] = r4[2]; bl[nt*2+1][1] = r4[3];
            }
            #pragma unroll
            for (int mi = 0; mi < 2; ++mi) {
                const int row = wm * 32 + mi * 16 + a_row_l;
                const int col = kc + a_col_l;
                uint32_t ah[4], al[4];
                ldm_x4(ah, sAh + (row * GPAD + col) * 2);
                ldm_x4(al, sAl + (row * GPAD + col) * 2);
                #pragma unroll
                for (int ni = 0; ni < 4; ++ni) {
                    mma_bf16(acc[mi][ni], ah, bh[ni]);
                    mma_bf16(acc[mi][ni], ah, bl[ni]);
                    mma_bf16(acc[mi][ni], al, bh[ni]);
                }
            }
        }
    }

    const int lr = lane >> 2;
    const int lc = (lane & 3) * 2;

    #pragma unroll
    for (int mi = 0; mi < 2; ++mi) {
        #pragma unroll
        for (int half = 0; half < 2; ++half) {
            const int m = bm + wm * 32 + mi * 16 + lr + half * 8;
            const int s_pos = m & (Ss - 1);
            const int b_idx = m >> 11;
            #pragma unroll
            for (int ni = 0; ni < 4; ++ni) {
                const int nl = wn * 32 + ni * 8 + lc;
                const int n = bn + nl;
                float f0 = acc[mi][ni][half * 2 + 0] + sbias[nl];
                float f1 = acc[mi][ni][half * 2 + 1] + sbias[nl + 1];

                if (mode & 2) {
                    const int d0 = n & 63;
                    const int j0 = d0 & 31;
                    const int j1 = (d0 + 1) & 31;
                    const float inv0 = 1.0f / powf(10000.0f, (float)j0 * (1.0f / 32.0f));
                    const float inv1 = 1.0f / powf(10000.0f, (float)j1 * (1.0f / 32.0f));
                    float s0, c0, s1, c1;
                    sincosf((float)s_pos * inv0, &s0, &c0);
                    sincosf((float)s_pos * inv1, &s1, &c1);
                    const float x0 = f0, x1 = f1;
                    f0 = x0 * c0 - x1 * s1;
                    f1 = x0 * s0 + x1 * c1;
                }

                if (mode & 1) {
                    const int h = n >> 6, d = n & 63;
                    const size_t idx =
                        (((size_t)b_idx * Hh + h) * Ss + s_pos) * DKk + d;
                    const __nv_bfloat16 h0 = __float2bfloat16_rn(f0);
                    const __nv_bfloat16 h1 = __float2bfloat16_rn(f1);
                    *(uint32_t*)(Ch + idx) = pack2(h0, h1);
                    *(uint32_t*)(Cl + idx) =
                        pack2(__float2bfloat16_rn(f0 - __bfloat162float(h0)),
                              __float2bfloat16_rn(f1 - __bfloat162float(h1)));
                } else {
                    *(float2*)(Cf + (size_t)m * Dd + n) = make_float2(f0, f1);
                }
            }
        }
    }
}

// ---------------------------------------------------------------------------
// Causal flash attention, bf16 mma.sync, pre-split inputs, cp.async 2-stage.
// CTA = 128 queries of one (b,h); 8 warps x 16 query rows; 64-key blocks.
// SMEM: Qh,Ql [128][GPAD]; 2 stages of {Kh,Kl,Vh,Vl}[64][GPAD].
// ---------------------------------------------------------------------------
#define STAGE_ELEMS (4 * 64 * GPAD)

__global__ __launch_bounds__(256, 1) void attn_mma()
{
    extern __shared__ __nv_bfloat16 smb[];
    __nv_bfloat16* Qh = smb;
    __nv_bfloat16* Ql = Qh + 128 * GPAD;
    __nv_bfloat16* Stg = Ql + 128 * GPAD;   // stage s at Stg + s*STAGE_ELEMS

    const int qb = gridDim.x - 1 - blockIdx.x;   // heavy blocks first
    const int bh = blockIdx.y;
    const int bidx = bh >> 4;
    const int head = bh & 15;
    const int tid = threadIdx.x;
    const int lane = tid & 31;
    const int w = tid >> 5;
    const int wq = w * 16;

    const __nv_bfloat16* qhg = g_qh + ((size_t)bh * Ss + (size_t)qb * 128) * DKk;
    const __nv_bfloat16* qlg = g_ql + ((size_t)bh * Ss + (size_t)qb * 128) * DKk;
    const __nv_bfloat16* khg = g_kh + (size_t)bh * Ss * DKk;
    const __nv_bfloat16* klg = g_kl + (size_t)bh * Ss * DKk;
    const __nv_bfloat16* vhg = g_vh + (size_t)bh * Ss * DKk;
    const __nv_bfloat16* vlg = g_vl + (size_t)bh * Ss * DKk;

    const uint32_t sQh = smem_u32(Qh), sQl = smem_u32(Ql);
    const uint32_t sStg = smem_u32(Stg);

    // fill Q (pure copy of pre-split bf16)
    #pragma unroll
    for (int e = tid; e < 1024; e += 256) {
        const int r = e >> 3, c = (e & 7) * 8;
        *(uint4*)(Qh + r * GPAD + c) = *(const uint4*)(qhg + r * 64 + c);
        *(uint4*)(Ql + r * GPAD + c) = *(const uint4*)(qlg + r * 64 + c);
    }

    const int nkb = 2 * qb + 2;

    // cp.async fill of one 64-key stage (4 matrices)
    const int f_r = tid >> 3;            // 0..31 (x2 with +32)
    const int f_c = (tid & 7) * 8;       // bf16 elems
    auto fill_stage = [&](int stage, int kb) {
        const size_t gofs = (size_t)kb * 64 * DKk;
        const uint32_t sb = sStg + stage * STAGE_ELEMS * 2;
        #pragma unroll
        for (int i = 0; i < 2; ++i) {
            const int r = f_r + i * 32;
            const uint32_t so = (r * GPAD + f_c) * 2;
            const size_t go = gofs + r * 64 + f_c;
            CP16(sb + 0 * 64 * GPAD * 2 + so, khg + go);
            CP16(sb + 1 * 64 * GPAD * 2 + so, klg + go);
            CP16(sb + 2 * 64 * GPAD * 2 + so, vhg + go);
            CP16(sb + 3 * 64 * GPAD * 2 + so, vlg + go);
        }
        CP_COMMIT();
    };

    fill_stage(0, 0);
    __syncthreads();   // Q visible

    const int a_row = lane & 15;
    const int a_col = (lane & 16) >> 1;
    const int b_row = (lane & 7) + ((lane & 16) >> 1);
    const int b_col = lane & 8;
    const int v_key = ((lane >> 3) & 1) * 8 + (lane & 7);
    const int v_dim = (lane >> 4) * 8;

    uint32_t qfh[4][4], qfl[4][4];
    #pragma unroll
    for (int kt = 0; kt < 4; ++kt) {
        const uint32_t off = ((wq + a_row) * GPAD + kt * 16 + a_col) * 2;
        ldm_x4(qfh[kt], sQh + off);
        ldm_x4(qfl[kt], sQl + off);
    }

    float O[8][4];
    #pragma unroll
    for (int nf = 0; nf < 8; ++nf)
        #pragma unroll
        for (int j = 0; j < 4; ++j) O[nf][j] = 0.f;
    float mrow[2] = {-INFINITY, -INFINITY};
    float lrow[2] = {0.f, 0.f};

    const int lr = lane >> 2;
    const int lc2 = (lane & 3) * 2;
    const int q0 = qb * 128 + wq + lr;
    const int warp_qmax = qb * 128 + wq + 15;

    for (int kb = 0; kb < nkb; ++kb) {
        const int st = kb & 1;
        CP_WAIT0();
        __syncthreads();
        if (kb + 1 < nkb) fill_stage(st ^ 1, kb + 1);

        if (kb * 64 > warp_qmax) continue;

        const uint32_t sKh = sStg + (st * STAGE_ELEMS + 0 * 64 * GPAD) * 2;
        const uint32_t sKl = sStg + (st * STAGE_ELEMS + 1 * 64 * GPAD) * 2;
        const uint32_t sVh = sStg + (st * STAGE_ELEMS + 2 * 64 * GPAD) * 2;
        const uint32_t sVl = sStg + (st * STAGE_ELEMS + 3 * 64 * GPAD) * 2;

        // ---- scores = Q K^T (hh + hl + lh) ----
        float acc[8][4];
        #pragma unroll
        for (int nf = 0; nf < 8; ++nf)
            #pragma unroll
            for (int j = 0; j < 4; ++j) acc[nf][j] = 0.f;

        #pragma unroll
        for (int kt = 0; kt < 4; ++kt) {
            const int kc = kt * 16;
            #pragma unroll
            for (int ntp = 0; ntp < 4; ++ntp) {
                uint32_t rh[4], rl[4];
                const uint32_t off = ((ntp * 16 + b_row) * GPAD + kc + b_col) * 2;
                ldm_x4(rh, sKh + off);
                ldm_x4(rl, sKl + off);
                uint32_t b0h[2] = {rh[0], rh[1]}, b1h[2] = {rh[2], rh[3]};
                uint32_t b0l[2] = {rl[0], rl[1]}, b1l[2] = {rl[2], rl[3]};
                mma_bf16(acc[2*ntp],   qfh[kt], b0h);
                mma_bf16(acc[2*ntp],   qfh[kt], b0l);
                mma_bf16(acc[2*ntp],   qfl[kt], b0h);
                mma_bf16(acc[2*ntp+1], qfh[kt], b1h);
                mma_bf16(acc[2*ntp+1], qfh[kt], b1l);
                mma_bf16(acc[2*ntp+1], qfl[kt], b1h);
            }
        }

        // ---- scale + causal mask ----
        const bool diag = (kb >= 2 * qb);
        #pragma unroll
        for (int nf = 0; nf < 8; ++nf) {
            #pragma unroll
            for (int j = 0; j < 4; ++j) {
                const float v = acc[nf][j] * 0.125f;
                if (diag) {
                    const int kgl = kb * 64 + nf * 8 + lc2 + (j & 1);
                    const int qgl = q0 + 8 * (j >> 1);
                    acc[nf][j] = (kgl <= qgl) ? v : -1e30f;
                } else {
                    acc[nf][j] = v;
                }
            }
        }

        // ---- online softmax (per row-half) ----
        #pragma unroll
        for (int half = 0; half < 2; ++half) {
            float rm = -1e30f;
            #pragma unroll
            for (int nf = 0; nf < 8; ++nf)
                rm = fmaxf(rm, fmaxf(acc[nf][2*half], acc[nf][2*half+1]));
            rm = fmaxf(rm, __shfl_xor_sync(0xffffffffu, rm, 1));
            rm = fmaxf(rm, __shfl_xor_sync(0xffffffffu, rm, 2));
            const float mn = fmaxf(mrow[half], rm);
            const float alpha = __expf(mrow[half] - mn);
            mrow[half] = mn;
            float rs = 0.f;
            #pragma unroll
            for (int nf = 0; nf < 8; ++nf) {
                const float p0 = __expf(acc[nf][2*half]   - mn);
                const float p1 = __expf(acc[nf][2*half+1] - mn);
                acc[nf][2*half]   = p0;
                acc[nf][2*half+1] = p1;
                rs += p0 + p1;
            }
            rs += __shfl_xor_sync(0xffffffffu, rs, 1);
            rs += __shfl_xor_sync(0xffffffffu, rs, 2);
            lrow[half] = lrow[half] * alpha + rs;
            #pragma unroll
            for (int nf = 0; nf < 8; ++nf) {
                O[nf][2*half]   *= alpha;
                O[nf][2*half+1] *= alpha;
            }
        }

        // ---- O += P V (hh + hl + lh) ----
        #pragma unroll
        for (int kt = 0; kt < 4; ++kt) {
            uint32_t ah[4], al[4];
            #pragma unroll
            for (int f = 0; f < 4; ++f) {
                const float p0 = acc[2*kt + (f >> 1)][(f & 1) * 2 + 0];
                const float p1 = acc[2*kt + (f >> 1)][(f & 1) * 2 + 1];
                const __nv_bfloat16 h0 = __float2bfloat16_rn(p0);
                const __nv_bfloat16 h1 = __float2bfloat16_rn(p1);
                ah[f] = pack2(h0, h1);
                al[f] = pack2(__float2bfloat16_rn(p0 - __bfloat162float(h0)),
                              __float2bfloat16_rn(p1 - __bfloat162float(h1)));
            }
            #pragma unroll
            for (int nd = 0; nd < 4; ++nd) {
                uint32_t vh4[4], vl4[4];
                const uint32_t off = ((kt * 16 + v_key) * GPAD + nd * 16 + v_dim) * 2;
                ldm_x4_t(vh4, sVh + off);
                ldm_x4_t(vl4, sVl + off);
                uint32_t b0h[2] = {vh4[0], vh4[1]}, b1h[2] = {vh4[2], vh4[3]};
                uint32_t b0l[2] = {vl4[0], vl4[1]}, b1l[2] = {vl4[2], vl4[3]};
                mma_bf16(O[2*nd],   ah, b0h);
                mma_bf16(O[2*nd],   ah, b0l);
                mma_bf16(O[2*nd],   al, b0h);
                mma_bf16(O[2*nd+1], ah, b1h);
                mma_bf16(O[2*nd+1], ah, b1l);
                mma_bf16(O[2*nd+1], al, b1h);
            }
        }
    }

    // ---- normalize + split-store to g_ath/g_atl [B,S,D] ----
    #pragma unroll
    for (int half = 0; half < 2; ++half) {
        const int qgl = q0 + 8 * half;
        const float inv = 1.0f / lrow[half];
        const size_t base = ((size_t)bidx * Ss + qgl) * Dd + head * 64;
        #pragma unroll
        for (int nf = 0; nf < 8; ++nf) {
            const float f0 = O[nf][2*half] * inv;
            const float f1 = O[nf][2*half+1] * inv;
            const __nv_bfloat16 h0 = __float2bfloat16_rn(f0);
            const __nv_bfloat16 h1 = __float2bfloat16_rn(f1);
            *(uint32_t*)(g_ath + base + nf * 8 + lc2) = pack2(h0, h1);
            *(uint32_t*)(g_atl + base + nf * 8 + lc2) =
                pack2(__float2bfloat16_rn(f0 - __bfloat162float(h0)),
                      __float2bfloat16_rn(f1 - __bfloat162float(h1)));
        }
    }
}

// ---------------------------------------------------------------------------
extern "C" void kernel_launch(void* const* d_in, const int* in_sizes, int n_in,
                              void* d_out, int out_size)
{
    const float* query = (const float*)d_in[0];
    const float* key   = (const float*)d_in[1];
    const float* value = (const float*)d_in[2];
    const float* Wq = (const float*)d_in[3];
    const float* bq = (const float*)d_in[4];
    const float* Wk = (const float*)d_in[5];
    const float* bk = (const float*)d_in[6];
    const float* Wv = (const float*)d_in[7];
    const float* bv = (const float*)d_in[8];
    const float* Wo = (const float*)d_in[9];
    const float* bo = (const float*)d_in[10];
    float* out = (float*)d_out;

    __nv_bfloat16 *qh, *ql, *kh, *kl, *vh, *vl, *ath, *atl, *wth, *wtl;
    cudaGetSymbolAddress((void**)&qh, g_qh);
    cudaGetSymbolAddress((void**)&ql, g_ql);
    cudaGetSymbolAddress((void**)&kh, g_kh);
    cudaGetSymbolAddress((void**)&kl, g_kl);
    cudaGetSymbolAddress((void**)&vh, g_vh);
    cudaGetSymbolAddress((void**)&vl, g_vl);
    cudaGetSymbolAddress((void**)&ath, g_ath);
    cudaGetSymbolAddress((void**)&atl, g_atl);
    cudaGetSymbolAddress((void**)&wth, g_wth);
    cudaGetSymbolAddress((void**)&wtl, g_wtl);

    dim3 tgrid(32, 32), tblk(32, 8);
    transpose_split<<<tgrid, tblk>>>(Wq, wth + 0u * 1048576, wtl + 0u * 1048576);
    transpose_split<<<tgrid, tblk>>>(Wk, wth + 1u * 1048576, wtl + 1u * 1048576);
    transpose_split<<<tgrid, tblk>>>(Wv, wth + 2u * 1048576, wtl + 2u * 1048576);
    transpose_split<<<tgrid, tblk>>>(Wo, wth + 3u * 1048576, wtl + 3u * 1048576);

    const int gsmem = 4 * 128 * GPAD * (int)sizeof(__nv_bfloat16);  // 73728
    cudaFuncSetAttribute(gemm_mma, cudaFuncAttributeMaxDynamicSharedMemorySize, gsmem);

    dim3 ggrid(Dd / 128, (Bb * Ss) / 128);    // (8, 32)
    gemm_mma<<<ggrid, 512, gsmem>>>(query, nullptr, nullptr,
        wth + 0u * 1048576, wtl + 0u * 1048576, bq, nullptr, qh, ql, 3);
    gemm_mma<<<ggrid, 512, gsmem>>>(key, nullptr, nullptr,
        wth + 1u * 1048576, wtl + 1u * 1048576, bk, nullptr, kh, kl, 3);
    gemm_mma<<<ggrid, 512, gsmem>>>(value, nullptr, nullptr,
        wth + 2u * 1048576, wtl + 2u * 1048576, bv, nullptr, vh, vl, 1);

    const int asmem = (2 * 128 * GPAD + 2 * STAGE_ELEMS) *
                      (int)sizeof(__nv_bfloat16);   // 110592
    cudaFuncSetAttribute(attn_mma, cudaFuncAttributeMaxDynamicSharedMemorySize, asmem);
    attn_mma<<<dim3(Ss / 128, Bb * Hh), 256, asmem>>>();

    gemm_mma<<<ggrid, 512, gsmem>>>(nullptr, ath, atl,
        wth + 3u * 1048576, wtl + 3u * 1048576, bo, out, nullptr, nullptr, 4);
}

// round 6
// speedup vs baseline: 3.4960x; 1.1119x over previous
#include <cuda_runtime.h>
#include <cuda_bf16.h>
#include <math.h>
#include <stdint.h>

#define Bb 2
#define Ss 2048
#define Dd 1024
#define Hh 16
#define DKk 64
#define GPAD 72   // bf16 columns per SMEM row (144 B stride, ldmatrix conflict-free)

// Scratch (device globals: allocation-free rule). All pre-split bf16 hi/lo.
#define QKV_ELEMS ((size_t)Bb * Hh * Ss * DKk)
__device__ __nv_bfloat16 g_qh[QKV_ELEMS], g_ql[QKV_ELEMS];
__device__ __nv_bfloat16 g_kh[QKV_ELEMS], g_kl[QKV_ELEMS];
__device__ __nv_bfloat16 g_vh[QKV_ELEMS], g_vl[QKV_ELEMS];
__device__ __nv_bfloat16 g_ath[(size_t)Bb * Ss * Dd], g_atl[(size_t)Bb * Ss * Dd];
__device__ __nv_bfloat16 g_wth[4 * 1024 * 1024], g_wtl[4 * 1024 * 1024];
__device__ __nv_bfloat16 g_insh[3 * 4194304], g_insl[3 * 4194304]; // split inputs

// ---------------------------------------------------------------------------
__device__ __forceinline__ uint32_t smem_u32(const void* p) {
    uint32_t a;
    asm("{ .reg .u64 t; cvta.to.shared.u64 t, %1; cvt.u32.u64 %0, t; }"
        : "=r"(a) : "l"(p));
    return a;
}

__device__ __forceinline__ void ldm_x4(uint32_t* r, uint32_t addr) {
    asm volatile("ldmatrix.sync.aligned.m8n8.x4.shared.b16 {%0,%1,%2,%3}, [%4];"
        : "=r"(r[0]), "=r"(r[1]), "=r"(r[2]), "=r"(r[3]) : "r"(addr));
}

__device__ __forceinline__ void ldm_x4_t(uint32_t* r, uint32_t addr) {
    asm volatile("ldmatrix.sync.aligned.m8n8.x4.trans.shared.b16 {%0,%1,%2,%3}, [%4];"
        : "=r"(r[0]), "=r"(r[1]), "=r"(r[2]), "=r"(r[3]) : "r"(addr));
}

__device__ __forceinline__ void mma_bf16(float* d, const uint32_t* a,
                                         const uint32_t* b) {
    asm volatile(
        "mma.sync.aligned.m16n8k16.row.col.f32.bf16.bf16.f32 "
        "{%0,%1,%2,%3}, {%4,%5,%6,%7}, {%8,%9}, {%0,%1,%2,%3};"
        : "+f"(d[0]), "+f"(d[1]), "+f"(d[2]), "+f"(d[3])
        : "r"(a[0]), "r"(a[1]), "r"(a[2]), "r"(a[3]), "r"(b[0]), "r"(b[1]));
}

#define CP16(dst, src) \
    asm volatile("cp.async.ca.shared.global [%0], [%1], 16;" \
        :: "r"((uint32_t)(dst)), "l"(src) : "memory")
#define CP_COMMIT() asm volatile("cp.async.commit_group;" ::: "memory")
#define CP_WAIT0()  asm volatile("cp.async.wait_group 0;" ::: "memory")

__device__ __forceinline__ uint32_t pack2(__nv_bfloat16 a, __nv_bfloat16 b) {
    return (uint32_t)__bfloat16_as_ushort(a) |
           ((uint32_t)__bfloat16_as_ushort(b) << 16);
}

// split a float4 into hi/lo bf16 quads and store
__device__ __forceinline__ void split4(float4 x, __nv_bfloat16* hp,
                                       __nv_bfloat16* lp) {
    ushort4 hu, lu;
    __nv_bfloat16 h;
    h = __float2bfloat16_rn(x.x); hu.x = __bfloat16_as_ushort(h);
    lu.x = __bfloat16_as_ushort(__float2bfloat16_rn(x.x - __bfloat162float(h)));
    h = __float2bfloat16_rn(x.y); hu.y = __bfloat16_as_ushort(h);
    lu.y = __bfloat16_as_ushort(__float2bfloat16_rn(x.y - __bfloat162float(h)));
    h = __float2bfloat16_rn(x.z); hu.z = __bfloat16_as_ushort(h);
    lu.z = __bfloat16_as_ushort(__float2bfloat16_rn(x.z - __bfloat162float(h)));
    h = __float2bfloat16_rn(x.w); hu.w = __bfloat16_as_ushort(h);
    lu.w = __bfloat16_as_ushort(__float2bfloat16_rn(x.w - __bfloat162float(h)));
    *(ushort4*)hp = hu;
    *(ushort4*)lp = lu;
}

// ---------------------------------------------------------------------------
// Batched weight transpose + split: Wth/Wtl[z][n][k] = split(W_z[k][n])
// ---------------------------------------------------------------------------
__global__ void transpose_split4(const float* __restrict__ W0,
                                 const float* __restrict__ W1,
                                 const float* __restrict__ W2,
                                 const float* __restrict__ W3,
                                 __nv_bfloat16* __restrict__ Wth,
                                 __nv_bfloat16* __restrict__ Wtl)
{
    __shared__ float t[32][33];
    const int z = blockIdx.z;
    const float* W = (z == 0) ? W0 : (z == 1) ? W1 : (z == 2) ? W2 : W3;
    __nv_bfloat16* oh = Wth + (size_t)z * 1048576;
    __nv_bfloat16* ol = Wtl + (size_t)z * 1048576;

    const int bx = blockIdx.x * 32, by = blockIdx.y * 32;
    #pragma unroll
    for (int i = threadIdx.y; i < 32; i += 8)
        t[i][threadIdx.x] = W[(size_t)(by + i) * 1024 + bx + threadIdx.x];
    __syncthreads();
    #pragma unroll
    for (int i = threadIdx.y; i < 32; i += 8) {
        const float v = t[threadIdx.x][i];
        const __nv_bfloat16 h = __float2bfloat16_rn(v);
        const size_t idx = (size_t)(bx + i) * 1024 + by + threadIdx.x;
        oh[idx] = h;
        ol[idx] = __float2bfloat16_rn(v - __bfloat162float(h));
    }
}

// ---------------------------------------------------------------------------
// Batched input split: fp32 [4096x1024] x3 -> bf16 hi/lo (row-major)
// ---------------------------------------------------------------------------
__global__ void split_inputs(const float* __restrict__ X0,
                             const float* __restrict__ X1,
                             const float* __restrict__ X2)
{
    const int z = blockIdx.z;
    const float* X = (z == 0) ? X0 : (z == 1) ? X1 : X2;
    __nv_bfloat16* oh = g_insh + (size_t)z * 4194304;
    __nv_bfloat16* ol = g_insl + (size_t)z * 4194304;
    const size_t e = ((size_t)blockIdx.x * 256 + threadIdx.x) * 4;
    split4(*(const float4*)(X + e), oh + e, ol + e);
}

// ---------------------------------------------------------------------------
// Error-compensated bf16 mma.sync GEMM, all operands pre-split, cp.async
// 2-stage pipelined. C = A @ Bt^T (+bias).
// mode: bit0 = head-split bf16 hi/lo output (+bias+maybe rope),
//       bit1 = fuse RoPE. bit0 clear = fp32 row-major to Cf.
// ---------------------------------------------------------------------------
#define GSTAGE (4 * 128 * GPAD)   // elems per stage (Ah,Al,Bh,Bl)

__global__ __launch_bounds__(512, 1) void gemm_mma(
    const __nv_bfloat16* __restrict__ Ahg, const __nv_bfloat16* __restrict__ Alg,
    const __nv_bfloat16* __restrict__ Bth, const __nv_bfloat16* __restrict__ Btl,
    const float* __restrict__ bias, float* __restrict__ Cf,
    __nv_bfloat16* __restrict__ Ch, __nv_bfloat16* __restrict__ Cl, int mode)
{
    extern __shared__ __nv_bfloat16 smg[];
    __shared__ float sbias[128];

    const int tid = threadIdx.x;
    const int bm = blockIdx.y * 128;
    const int bn = blockIdx.x * 128;

    if (tid < 128) sbias[tid] = bias[bn + tid];

    const int lane = tid & 31;
    const int w = tid >> 5;
    const int wm = w & 3;
    const int wn = w >> 2;

    const uint32_t sbase = smem_u32(smg);

    // cp.async fill of one stage (Ah,Al,Bh,Bl), K-chunk = 64 bf16 cols
    const int f_r = tid >> 3;          // 0..63
    const int f_c = (tid & 7) * 8;     // bf16 col
    auto fill = [&](int stage, int chunk) {
        const int k0 = chunk * 64;
        const uint32_t sb = sbase + stage * GSTAGE * 2;
        #pragma unroll
        for (int i = 0; i < 2; ++i) {
            const int r = f_r + i * 64;
            const uint32_t so = (r * GPAD + f_c) * 2;
            CP16(sb + 0 * 128 * GPAD * 2 + so, Ahg + (size_t)(bm + r) * 1024 + k0 + f_c);
            CP16(sb + 1 * 128 * GPAD * 2 + so, Alg + (size_t)(bm + r) * 1024 + k0 + f_c);
            CP16(sb + 2 * 128 * GPAD * 2 + so, Bth + (size_t)(bn + r) * 1024 + k0 + f_c);
            CP16(sb + 3 * 128 * GPAD * 2 + so, Btl + (size_t)(bn + r) * 1024 + k0 + f_c);
        }
        CP_COMMIT();
    };

    float acc[2][4][4];
    #pragma unroll
    for (int mi = 0; mi < 2; mi++)
        #pragma unroll
        for (int ni = 0; ni < 4; ni++)
            #pragma unroll
            for (int q = 0; q < 4; q++) acc[mi][ni][q] = 0.f;

    const int a_row_l = (lane & 15);
    const int a_col_l = ((lane & 16) >> 1);
    const int b_row_l = (lane & 7) + ((lane & 16) >> 1);
    const int b_col_l = (lane & 8);

    fill(0, 0);

    for (int chunk = 0; chunk < 16; ++chunk) {
        const int st = chunk & 1;
        CP_WAIT0();
        __syncthreads();
        if (chunk + 1 < 16) fill(st ^ 1, chunk + 1);

        const uint32_t sAh = sbase + (st * GSTAGE + 0 * 128 * GPAD) * 2;
        const uint32_t sAl = sbase + (st * GSTAGE + 1 * 128 * GPAD) * 2;
        const uint32_t sBh = sbase + (st * GSTAGE + 2 * 128 * GPAD) * 2;
        const uint32_t sBl = sbase + (st * GSTAGE + 3 * 128 * GPAD) * 2;

        #pragma unroll
        for (int kk = 0; kk < 4; ++kk) {
            const int kc = kk * 16;
            uint32_t bh[4][2], bl[4][2];
            #pragma unroll
            for (int nt = 0; nt < 2; ++nt) {
                const int row = wn * 32 + nt * 16 + b_row_l;
                const int col = kc + b_col_l;
                uint32_t r4[4];
                ldm_x4(r4, sBh + (row * GPAD + col) * 2);
                bh[nt*2][0] = r4[0]; bh[nt*2][1] = r4[1];
                bh[nt*2+1][0] = r4[2]; bh[nt*2+1][1] = r4[3];
                ldm_x4(r4, sBl + (row * GPAD + col) * 2);
                bl[nt*2][0] = r4[0]; bl[nt*2][1] = r4[1];
                bl[nt*2+1][0] = r4[2]; bl[nt*2+1][1] = r4[3];
            }
            #pragma unroll
            for (int mi = 0; mi < 2; ++mi) {
                const int row = wm * 32 + mi * 16 + a_row_l;
                const int col = kc + a_col_l;
                uint32_t ah[4], al[4];
                ldm_x4(ah, sAh + (row * GPAD + col) * 2);
                ldm_x4(al, sAl + (row * GPAD + col) * 2);
                #pragma unroll
                for (int ni = 0; ni < 4; ++ni) {
                    mma_bf16(acc[mi][ni], ah, bh[ni]);
                    mma_bf16(acc[mi][ni], ah, bl[ni]);
                    mma_bf16(acc[mi][ni], al, bh[ni]);
                }
            }
        }
    }

    const int lr = lane >> 2;
    const int lc = (lane & 3) * 2;

    #pragma unroll
    for (int mi = 0; mi < 2; ++mi) {
        #pragma unroll
        for (int half = 0; half < 2; ++half) {
            const int m = bm + wm * 32 + mi * 16 + lr + half * 8;
            const int s_pos = m & (Ss - 1);
            const int b_idx = m >> 11;
            #pragma unroll
            for (int ni = 0; ni < 4; ++ni) {
                const int nl = wn * 32 + ni * 8 + lc;
                const int n = bn + nl;
                float f0 = acc[mi][ni][half * 2 + 0] + sbias[nl];
                float f1 = acc[mi][ni][half * 2 + 1] + sbias[nl + 1];

                if (mode & 2) {
                    const int d0 = n & 63;
                    const int j0 = d0 & 31;
                    const int j1 = (d0 + 1) & 31;
                    const float inv0 = 1.0f / powf(10000.0f, (float)j0 * (1.0f / 32.0f));
                    const float inv1 = 1.0f / powf(10000.0f, (float)j1 * (1.0f / 32.0f));
                    float s0, c0, s1, c1;
                    sincosf((float)s_pos * inv0, &s0, &c0);
                    sincosf((float)s_pos * inv1, &s1, &c1);
                    const float x0 = f0, x1 = f1;
                    f0 = x0 * c0 - x1 * s1;
                    f1 = x0 * s0 + x1 * c1;
                }

                if (mode & 1) {
                    const int h = n >> 6, d = n & 63;
                    const size_t idx =
                        (((size_t)b_idx * Hh + h) * Ss + s_pos) * DKk + d;
                    const __nv_bfloat16 h0 = __float2bfloat16_rn(f0);
                    const __nv_bfloat16 h1 = __float2bfloat16_rn(f1);
                    *(uint32_t*)(Ch + idx) = pack2(h0, h1);
                    *(uint32_t*)(Cl + idx) =
                        pack2(__float2bfloat16_rn(f0 - __bfloat162float(h0)),
                              __float2bfloat16_rn(f1 - __bfloat162float(h1)));
                } else {
                    *(float2*)(Cf + (size_t)m * Dd + n) = make_float2(f0, f1);
                }
            }
        }
    }
}

// ---------------------------------------------------------------------------
// Causal flash attention, bf16 mma.sync, pre-split, cp.async 2-stage,
// 128-key blocks. CTA = 128 queries of one (b,h); 8 warps x 16 q rows.
// ---------------------------------------------------------------------------
#define ASTAGE (4 * 128 * GPAD)   // elems per stage (Kh,Kl,Vh,Vl), 128 keys

__global__ __launch_bounds__(256, 1) void attn_mma()
{
    extern __shared__ __nv_bfloat16 smb[];
    __nv_bfloat16* Qh = smb;
    __nv_bfloat16* Ql = Qh + 128 * GPAD;
    __nv_bfloat16* Stg = Ql + 128 * GPAD;

    const int qb = gridDim.x - 1 - blockIdx.x;   // heavy blocks first
    const int bh = blockIdx.y;
    const int bidx = bh >> 4;
    const int head = bh & 15;
    const int tid = threadIdx.x;
    const int lane = tid & 31;
    const int w = tid >> 5;
    const int wq = w * 16;

    const __nv_bfloat16* qhg = g_qh + ((size_t)bh * Ss + (size_t)qb * 128) * DKk;
    const __nv_bfloat16* qlg = g_ql + ((size_t)bh * Ss + (size_t)qb * 128) * DKk;
    const __nv_bfloat16* khg = g_kh + (size_t)bh * Ss * DKk;
    const __nv_bfloat16* klg = g_kl + (size_t)bh * Ss * DKk;
    const __nv_bfloat16* vhg = g_vh + (size_t)bh * Ss * DKk;
    const __nv_bfloat16* vlg = g_vl + (size_t)bh * Ss * DKk;

    const uint32_t sQh = smem_u32(Qh), sQl = smem_u32(Ql);
    const uint32_t sStg = smem_u32(Stg);

    // fill Q (pure copy of pre-split bf16)
    #pragma unroll
    for (int e = tid; e < 1024; e += 256) {
        const int r = e >> 3, c = (e & 7) * 8;
        *(uint4*)(Qh + r * GPAD + c) = *(const uint4*)(qhg + r * 64 + c);
        *(uint4*)(Ql + r * GPAD + c) = *(const uint4*)(qlg + r * 64 + c);
    }

    const int nkb = qb + 1;

    // cp.async fill of one 128-key stage (4 matrices)
    const int f_r = tid >> 3;            // 0..31 (+32,+64,+96)
    const int f_c = (tid & 7) * 8;
    auto fill_stage = [&](int stage, int kb) {
        const size_t gofs = (size_t)kb * 128 * DKk;
        const uint32_t sb = sStg + stage * ASTAGE * 2;
        #pragma unroll
        for (int i = 0; i < 4; ++i) {
            const int r = f_r + i * 32;
            const uint32_t so = (r * GPAD + f_c) * 2;
            const size_t go = gofs + r * 64 + f_c;
            CP16(sb + 0 * 128 * GPAD * 2 + so, khg + go);
            CP16(sb + 1 * 128 * GPAD * 2 + so, klg + go);
            CP16(sb + 2 * 128 * GPAD * 2 + so, vhg + go);
            CP16(sb + 3 * 128 * GPAD * 2 + so, vlg + go);
        }
        CP_COMMIT();
    };

    fill_stage(0, 0);
    __syncthreads();   // Q visible

    const int a_row = lane & 15;
    const int a_col = (lane & 16) >> 1;
    const int b_row = (lane & 7) + ((lane & 16) >> 1);
    const int b_col = lane & 8;
    const int v_key = ((lane >> 3) & 1) * 8 + (lane & 7);
    const int v_dim = (lane >> 4) * 8;

    uint32_t qfh[4][4], qfl[4][4];
    #pragma unroll
    for (int kt = 0; kt < 4; ++kt) {
        const uint32_t off = ((wq + a_row) * GPAD + kt * 16 + a_col) * 2;
        ldm_x4(qfh[kt], sQh + off);
        ldm_x4(qfl[kt], sQl + off);
    }

    float O[8][4];
    #pragma unroll
    for (int nf = 0; nf < 8; ++nf)
        #pragma unroll
        for (int j = 0; j < 4; ++j) O[nf][j] = 0.f;
    float mrow[2] = {-INFINITY, -INFINITY};
    float lrow[2] = {0.f, 0.f};

    const int lr = lane >> 2;
    const int lc2 = (lane & 3) * 2;
    const int q0 = qb * 128 + wq + lr;

    for (int kb = 0; kb < nkb; ++kb) {
        const int st = kb & 1;
        CP_WAIT0();
        __syncthreads();
        if (kb + 1 < nkb) fill_stage(st ^ 1, kb + 1);

        const uint32_t sKh = sStg + (st * ASTAGE + 0 * 128 * GPAD) * 2;
        const uint32_t sKl = sStg + (st * ASTAGE + 1 * 128 * GPAD) * 2;
        const uint32_t sVh = sStg + (st * ASTAGE + 2 * 128 * GPAD) * 2;
        const uint32_t sVl = sStg + (st * ASTAGE + 3 * 128 * GPAD) * 2;

        // ---- scores = Q K^T (hh + hl + lh), 16 key octets ----
        float acc[16][4];
        #pragma unroll
        for (int nf = 0; nf < 16; ++nf)
            #pragma unroll
            for (int j = 0; j < 4; ++j) acc[nf][j] = 0.f;

        #pragma unroll
        for (int kt = 0; kt < 4; ++kt) {
            const int kc = kt * 16;
            #pragma unroll
            for (int ntp = 0; ntp < 8; ++ntp) {
                uint32_t rh[4], rl[4];
                const uint32_t off = ((ntp * 16 + b_row) * GPAD + kc + b_col) * 2;
                ldm_x4(rh, sKh + off);
                ldm_x4(rl, sKl + off);
                uint32_t b0h[2] = {rh[0], rh[1]}, b1h[2] = {rh[2], rh[3]};
                uint32_t b0l[2] = {rl[0], rl[1]}, b1l[2] = {rl[2], rl[3]};
                mma_bf16(acc[2*ntp],   qfh[kt], b0h);
                mma_bf16(acc[2*ntp],   qfh[kt], b0l);
                mma_bf16(acc[2*ntp],   qfl[kt], b0h);
                mma_bf16(acc[2*ntp+1], qfh[kt], b1h);
                mma_bf16(acc[2*ntp+1], qfh[kt], b1l);
                mma_bf16(acc[2*ntp+1], qfl[kt], b1h);
            }
        }

        // ---- scale + causal mask ----
        const bool diag = (kb == qb);
        #pragma unroll
        for (int nf = 0; nf < 16; ++nf) {
            #pragma unroll
            for (int j = 0; j < 4; ++j) {
                const float v = acc[nf][j] * 0.125f;
                if (diag) {
                    const int kgl = kb * 128 + nf * 8 + lc2 + (j & 1);
                    const int qgl = q0 + 8 * (j >> 1);
                    acc[nf][j] = (kgl <= qgl) ? v : -1e30f;
                } else {
                    acc[nf][j] = v;
                }
            }
        }

        // ---- online softmax (per row-half) ----
        #pragma unroll
        for (int half = 0; half < 2; ++half) {
            float rm = -1e30f;
            #pragma unroll
            for (int nf = 0; nf < 16; ++nf)
                rm = fmaxf(rm, fmaxf(acc[nf][2*half], acc[nf][2*half+1]));
            rm = fmaxf(rm, __shfl_xor_sync(0xffffffffu, rm, 1));
            rm = fmaxf(rm, __shfl_xor_sync(0xffffffffu, rm, 2));
            const float mn = fmaxf(mrow[half], rm);
            const float alpha = __expf(mrow[half] - mn);
            mrow[half] = mn;
            float rs = 0.f;
            #pragma unroll
            for (int nf = 0; nf < 16; ++nf) {
                const float p0 = __expf(acc[nf][2*half]   - mn);
                const float p1 = __expf(acc[nf][2*half+1] - mn);
                acc[nf][2*half]   = p0;
                acc[nf][2*half+1] = p1;
                rs += p0 + p1;
            }
            rs += __shfl_xor_sync(0xffffffffu, rs, 1);
            rs += __shfl_xor_sync(0xffffffffu, rs, 2);
            lrow[half] = lrow[half] * alpha + rs;
            #pragma unroll
            for (int nf = 0; nf < 8; ++nf) {
                O[nf][2*half]   *= alpha;
                O[nf][2*half+1] *= alpha;
            }
        }

        // ---- O += P V (hh + hl + lh), 8 key chunks of 16 ----
        #pragma unroll
        for (int kt = 0; kt < 8; ++kt) {
            uint32_t ah[4], al[4];
            #pragma unroll
            for (int f = 0; f < 4; ++f) {
                const float p0 = acc[2*kt + (f >> 1)][(f & 1) * 2 + 0];
                const float p1 = acc[2*kt + (f >> 1)][(f & 1) * 2 + 1];
                const __nv_bfloat16 h0 = __float2bfloat16_rn(p0);
                const __nv_bfloat16 h1 = __float2bfloat16_rn(p1);
                ah[f] = pack2(h0, h1);
                al[f] = pack2(__float2bfloat16_rn(p0 - __bfloat162float(h0)),
                              __float2bfloat16_rn(p1 - __bfloat162float(h1)));
            }
            #pragma unroll
            for (int nd = 0; nd < 4; ++nd) {
                uint32_t vh4[4], vl4[4];
                const uint32_t off = ((kt * 16 + v_key) * GPAD + nd * 16 + v_dim) * 2;
                ldm_x4_t(vh4, sVh + off);
                ldm_x4_t(vl4, sVl + off);
                uint32_t b0h[2] = {vh4[0], vh4[1]}, b1h[2] = {vh4[2], vh4[3]};
                uint32_t b0l[2] = {vl4[0], vl4[1]}, b1l[2] = {vl4[2], vl4[3]};
                mma_bf16(O[2*nd],   ah, b0h);
                mma_bf16(O[2*nd],   ah, b0l);
                mma_bf16(O[2*nd],   al, b0h);
                mma_bf16(O[2*nd+1], ah, b1h);
                mma_bf16(O[2*nd+1], ah, b1l);
                mma_bf16(O[2*nd+1], al, b1h);
            }
        }
    }

    // ---- normalize + split-store to g_ath/g_atl [B,S,D] ----
    #pragma unroll
    for (int half = 0; half < 2; ++half) {
        const int qgl = q0 + 8 * half;
        const float inv = 1.0f / lrow[half];
        const size_t base = ((size_t)bidx * Ss + qgl) * Dd + head * 64;
        #pragma unroll
        for (int nf = 0; nf < 8; ++nf) {
            const float f0 = O[nf][2*half] * inv;
            const float f1 = O[nf][2*half+1] * inv;
            const __nv_bfloat16 h0 = __float2bfloat16_rn(f0);
            const __nv_bfloat16 h1 = __float2bfloat16_rn(f1);
            *(uint32_t*)(g_ath + base + nf * 8 + lc2) = pack2(h0, h1);
            *(uint32_t*)(g_atl + base + nf * 8 + lc2) =
                pack2(__float2bfloat16_rn(f0 - __bfloat162float(h0)),
                      __float2bfloat16_rn(f1 - __bfloat162float(h1)));
        }
    }
}

// ---------------------------------------------------------------------------
extern "C" void kernel_launch(void* const* d_in, const int* in_sizes, int n_in,
                              void* d_out, int out_size)
{
    const float* query = (const float*)d_in[0];
    const float* key   = (const float*)d_in[1];
    const float* value = (const float*)d_in[2];
    const float* Wq = (const float*)d_in[3];
    const float* bq = (const float*)d_in[4];
    const float* Wk = (const float*)d_in[5];
    const float* bk = (const float*)d_in[6];
    const float* Wv = (const float*)d_in[7];
    const float* bv = (const float*)d_in[8];
    const float* Wo = (const float*)d_in[9];
    const float* bo = (const float*)d_in[10];
    float* out = (float*)d_out;

    __nv_bfloat16 *qh, *ql, *kh, *kl, *vh, *vl, *ath, *atl, *wth, *wtl, *ish, *isl;
    cudaGetSymbolAddress((void**)&qh, g_qh);
    cudaGetSymbolAddress((void**)&ql, g_ql);
    cudaGetSymbolAddress((void**)&kh, g_kh);
    cudaGetSymbolAddress((void**)&kl, g_kl);
    cudaGetSymbolAddress((void**)&vh, g_vh);
    cudaGetSymbolAddress((void**)&vl, g_vl);
    cudaGetSymbolAddress((void**)&ath, g_ath);
    cudaGetSymbolAddress((void**)&atl, g_atl);
    cudaGetSymbolAddress((void**)&wth, g_wth);
    cudaGetSymbolAddress((void**)&wtl, g_wtl);
    cudaGetSymbolAddress((void**)&ish, g_insh);
    cudaGetSymbolAddress((void**)&isl, g_insl);

    transpose_split4<<<dim3(32, 32, 4), dim3(32, 8)>>>(Wq, Wk, Wv, Wo, wth, wtl);
    split_inputs<<<dim3(4096, 1, 3), 256>>>(query, key, value);

    const int gsmem = 2 * GSTAGE * (int)sizeof(__nv_bfloat16);   // 147456
    cudaFuncSetAttribute(gemm_mma, cudaFuncAttributeMaxDynamicSharedMemorySize, gsmem);

    dim3 ggrid(Dd / 128, (Bb * Ss) / 128);    // (8, 32)
    gemm_mma<<<ggrid, 512, gsmem>>>(ish + 0u * 4194304, isl + 0u * 4194304,
        wth + 0u * 1048576, wtl + 0u * 1048576, bq, nullptr, qh, ql, 3);
    gemm_mma<<<ggrid, 512, gsmem>>>(ish + 1u * 4194304, isl + 1u * 4194304,
        wth + 1u * 1048576, wtl + 1u * 1048576, bk, nullptr, kh, kl, 3);
    gemm_mma<<<ggrid, 512, gsmem>>>(ish + 2u * 4194304, isl + 2u * 4194304,
        wth + 2u * 1048576, wtl + 2u * 1048576, bv, nullptr, vh, vl, 1);

    const int asmem = (2 * 128 * GPAD + 2 * ASTAGE) *
                      (int)sizeof(__nv_bfloat16);   // 184320
    cudaFuncSetAttribute(attn_mma, cudaFuncAttributeMaxDynamicSharedMemorySize, asmem);
    attn_mma<<<dim3(Ss / 128, Bb * Hh), 256, asmem>>>();

    gemm_mma<<<ggrid, 512, gsmem>>>(ath, atl,
        wth + 3u * 1048576, wtl + 3u * 1048576, bo, out, nullptr, nullptr, 0);
}

// round 7
// speedup vs baseline: 3.6685x; 1.0494x over previous
#include <cuda_runtime.h>
#include <cuda_bf16.h>
#include <math.h>
#include <stdint.h>

#define Bb 2
#define Ss 2048
#define Dd 1024
#define Hh 16
#define DKk 64
#define GPAD 72   // bf16 columns per SMEM row (144 B stride, ldmatrix conflict-free)

// Scratch (device globals: allocation-free rule). All pre-split bf16 hi/lo.
#define QKV_ELEMS ((size_t)Bb * Hh * Ss * DKk)
__device__ __nv_bfloat16 g_qh[QKV_ELEMS], g_ql[QKV_ELEMS];
__device__ __nv_bfloat16 g_kh[QKV_ELEMS], g_kl[QKV_ELEMS];
__device__ __nv_bfloat16 g_vh[QKV_ELEMS], g_vl[QKV_ELEMS];
__device__ __nv_bfloat16 g_ath[(size_t)Bb * Ss * Dd], g_atl[(size_t)Bb * Ss * Dd];
__device__ __nv_bfloat16 g_wth[4 * 1024 * 1024], g_wtl[4 * 1024 * 1024];
__device__ __nv_bfloat16 g_insh[3 * 4194304], g_insl[3 * 4194304]; // split inputs

// ---------------------------------------------------------------------------
__device__ __forceinline__ uint32_t smem_u32(const void* p) {
    uint32_t a;
    asm("{ .reg .u64 t; cvta.to.shared.u64 t, %1; cvt.u32.u64 %0, t; }"
        : "=r"(a) : "l"(p));
    return a;
}

__device__ __forceinline__ void ldm_x4(uint32_t* r, uint32_t addr) {
    asm volatile("ldmatrix.sync.aligned.m8n8.x4.shared.b16 {%0,%1,%2,%3}, [%4];"
        : "=r"(r[0]), "=r"(r[1]), "=r"(r[2]), "=r"(r[3]) : "r"(addr));
}

__device__ __forceinline__ void ldm_x4_t(uint32_t* r, uint32_t addr) {
    asm volatile("ldmatrix.sync.aligned.m8n8.x4.trans.shared.b16 {%0,%1,%2,%3}, [%4];"
        : "=r"(r[0]), "=r"(r[1]), "=r"(r[2]), "=r"(r[3]) : "r"(addr));
}

__device__ __forceinline__ void mma_bf16(float* d, const uint32_t* a,
                                         const uint32_t* b) {
    asm volatile(
        "mma.sync.aligned.m16n8k16.row.col.f32.bf16.bf16.f32 "
        "{%0,%1,%2,%3}, {%4,%5,%6,%7}, {%8,%9}, {%0,%1,%2,%3};"
        : "+f"(d[0]), "+f"(d[1]), "+f"(d[2]), "+f"(d[3])
        : "r"(a[0]), "r"(a[1]), "r"(a[2]), "r"(a[3]), "r"(b[0]), "r"(b[1]));
}

#define CP16(dst, src) \
    asm volatile("cp.async.ca.shared.global [%0], [%1], 16;" \
        :: "r"((uint32_t)(dst)), "l"(src) : "memory")
#define CP_COMMIT() asm volatile("cp.async.commit_group;" ::: "memory")
#define CP_WAIT0()  asm volatile("cp.async.wait_group 0;" ::: "memory")

__device__ __forceinline__ uint32_t pack2(__nv_bfloat16 a, __nv_bfloat16 b) {
    return (uint32_t)__bfloat16_as_ushort(a) |
           ((uint32_t)__bfloat16_as_ushort(b) << 16);
}

__device__ __forceinline__ void split4(float4 x, __nv_bfloat16* hp,
                                       __nv_bfloat16* lp) {
    ushort4 hu, lu;
    __nv_bfloat16 h;
    h = __float2bfloat16_rn(x.x); hu.x = __bfloat16_as_ushort(h);
    lu.x = __bfloat16_as_ushort(__float2bfloat16_rn(x.x - __bfloat162float(h)));
    h = __float2bfloat16_rn(x.y); hu.y = __bfloat16_as_ushort(h);
    lu.y = __bfloat16_as_ushort(__float2bfloat16_rn(x.y - __bfloat162float(h)));
    h = __float2bfloat16_rn(x.z); hu.z = __bfloat16_as_ushort(h);
    lu.z = __bfloat16_as_ushort(__float2bfloat16_rn(x.z - __bfloat162float(h)));
    h = __float2bfloat16_rn(x.w); hu.w = __bfloat16_as_ushort(h);
    lu.w = __bfloat16_as_ushort(__float2bfloat16_rn(x.w - __bfloat162float(h)));
    *(ushort4*)hp = hu;
    *(ushort4*)lp = lu;
}

// ---------------------------------------------------------------------------
// Batched weight transpose + split
// ---------------------------------------------------------------------------
__global__ void transpose_split4(const float* __restrict__ W0,
                                 const float* __restrict__ W1,
                                 const float* __restrict__ W2,
                                 const float* __restrict__ W3,
                                 __nv_bfloat16* __restrict__ Wth,
                                 __nv_bfloat16* __restrict__ Wtl)
{
    __shared__ float t[32][33];
    const int z = blockIdx.z;
    const float* W = (z == 0) ? W0 : (z == 1) ? W1 : (z == 2) ? W2 : W3;
    __nv_bfloat16* oh = Wth + (size_t)z * 1048576;
    __nv_bfloat16* ol = Wtl + (size_t)z * 1048576;

    const int bx = blockIdx.x * 32, by = blockIdx.y * 32;
    #pragma unroll
    for (int i = threadIdx.y; i < 32; i += 8)
        t[i][threadIdx.x] = W[(size_t)(by + i) * 1024 + bx + threadIdx.x];
    __syncthreads();
    #pragma unroll
    for (int i = threadIdx.y; i < 32; i += 8) {
        const float v = t[threadIdx.x][i];
        const __nv_bfloat16 h = __float2bfloat16_rn(v);
        const size_t idx = (size_t)(bx + i) * 1024 + by + threadIdx.x;
        oh[idx] = h;
        ol[idx] = __float2bfloat16_rn(v - __bfloat162float(h));
    }
}

// ---------------------------------------------------------------------------
// Batched input split: fp32 [4096x1024] x3 -> bf16 hi/lo
// ---------------------------------------------------------------------------
__global__ void split_inputs(const float* __restrict__ X0,
                             const float* __restrict__ X1,
                             const float* __restrict__ X2)
{
    const int z = blockIdx.z;
    const float* X = (z == 0) ? X0 : (z == 1) ? X1 : X2;
    __nv_bfloat16* oh = g_insh + (size_t)z * 4194304;
    __nv_bfloat16* ol = g_insl + (size_t)z * 4194304;
    const size_t e = ((size_t)blockIdx.x * 256 + threadIdx.x) * 4;
    split4(*(const float4*)(X + e), oh + e, ol + e);
}

// ---------------------------------------------------------------------------
// Error-compensated bf16 mma.sync GEMM, fragment-double-buffered.
// FUSED=1: QKV fused, blockIdx.x = z*8 + ntile; rope for z<2; bf16 head-split
//          output. FUSED=0: single weight, fp32 row-major output to Cf.
// ---------------------------------------------------------------------------
#define GSTAGE (4 * 128 * GPAD)

template<int FUSED>
__global__ __launch_bounds__(512, 1) void gemm_mma(
    const __nv_bfloat16* __restrict__ Ahg_, const __nv_bfloat16* __restrict__ Alg_,
    const __nv_bfloat16* __restrict__ Wth, const __nv_bfloat16* __restrict__ Wtl,
    const float* __restrict__ b0, const float* __restrict__ b1,
    const float* __restrict__ b2, float* __restrict__ Cf,
    __nv_bfloat16* __restrict__ Ch0, __nv_bfloat16* __restrict__ Cl0,
    __nv_bfloat16* __restrict__ Ch1, __nv_bfloat16* __restrict__ Cl1,
    __nv_bfloat16* __restrict__ Ch2, __nv_bfloat16* __restrict__ Cl2)
{
    extern __shared__ __nv_bfloat16 smg[];
    __shared__ float sbias[128];

    const int tid = threadIdx.x;
    const int bx = blockIdx.x;
    const int z  = FUSED ? (bx >> 3) : 0;
    const int bn = FUSED ? ((bx & 7) * 128) : (bx * 128);
    const int bm = blockIdx.y * 128;

    const __nv_bfloat16* Ahg = FUSED ? Ahg_ + (size_t)z * 4194304 : Ahg_;
    const __nv_bfloat16* Alg = FUSED ? Alg_ + (size_t)z * 4194304 : Alg_;
    const __nv_bfloat16* Bth = Wth + (FUSED ? (size_t)z * 1048576 : 0);
    const __nv_bfloat16* Btl = Wtl + (FUSED ? (size_t)z * 1048576 : 0);
    const float* bias = FUSED ? (z == 0 ? b0 : (z == 1 ? b1 : b2)) : b0;

    if (tid < 128) sbias[tid] = bias[bn + tid];

    const int lane = tid & 31;
    const int w = tid >> 5;
    const int wm = w & 3;
    const int wn = w >> 2;

    const uint32_t sbase = smem_u32(smg);

    const int f_r = tid >> 3;
    const int f_c = (tid & 7) * 8;
    auto fill = [&](int stage, int chunk) {
        const int k0 = chunk * 64;
        const uint32_t sb = sbase + stage * GSTAGE * 2;
        #pragma unroll
        for (int i = 0; i < 2; ++i) {
            const int r = f_r + i * 64;
            const uint32_t so = (r * GPAD + f_c) * 2;
            CP16(sb + 0 * 128 * GPAD * 2 + so, Ahg + (size_t)(bm + r) * 1024 + k0 + f_c);
            CP16(sb + 1 * 128 * GPAD * 2 + so, Alg + (size_t)(bm + r) * 1024 + k0 + f_c);
            CP16(sb + 2 * 128 * GPAD * 2 + so, Bth + (size_t)(bn + r) * 1024 + k0 + f_c);
            CP16(sb + 3 * 128 * GPAD * 2 + so, Btl + (size_t)(bn + r) * 1024 + k0 + f_c);
        }
        CP_COMMIT();
    };

    float acc[2][4][4];
    #pragma unroll
    for (int mi = 0; mi < 2; mi++)
        #pragma unroll
        for (int ni = 0; ni < 4; ni++)
            #pragma unroll
            for (int q = 0; q < 4; q++) acc[mi][ni][q] = 0.f;

    const int a_row_l = (lane & 15);
    const int a_col_l = ((lane & 16) >> 1);
    const int b_row_l = (lane & 7) + ((lane & 16) >> 1);
    const int b_col_l = (lane & 8);

    fill(0, 0);

    for (int chunk = 0; chunk < 16; ++chunk) {
        const int st = chunk & 1;
        CP_WAIT0();
        __syncthreads();
        if (chunk + 1 < 16) fill(st ^ 1, chunk + 1);

        const uint32_t sAh = sbase + (st * GSTAGE + 0 * 128 * GPAD) * 2;
        const uint32_t sAl = sbase + (st * GSTAGE + 1 * 128 * GPAD) * 2;
        const uint32_t sBh = sbase + (st * GSTAGE + 2 * 128 * GPAD) * 2;
        const uint32_t sBl = sbase + (st * GSTAGE + 3 * 128 * GPAD) * 2;

        // double-buffered B fragments
        uint32_t BHf[2][4][2], BLf[2][4][2];
        auto loadB = [&](int buf, int kkq) {
            const int kc = kkq * 16;
            #pragma unroll
            for (int nt = 0; nt < 2; ++nt) {
                const int row = wn * 32 + nt * 16 + b_row_l;
                const int col = kc + b_col_l;
                uint32_t r4[4];
                ldm_x4(r4, sBh + (row * GPAD + col) * 2);
                BHf[buf][nt*2][0] = r4[0]; BHf[buf][nt*2][1] = r4[1];
                BHf[buf][nt*2+1][0] = r4[2]; BHf[buf][nt*2+1][1] = r4[3];
                ldm_x4(r4, sBl + (row * GPAD + col) * 2);
                BLf[buf][nt*2][0] = r4[0]; BLf[buf][nt*2][1] = r4[1];
                BLf[buf][nt*2+1][0] = r4[2]; BLf[buf][nt*2+1][1] = r4[3];
            }
        };

        loadB(0, 0);
        #pragma unroll
        for (int kk = 0; kk < 4; ++kk) {
            const int cur = kk & 1;
            const int col = kk * 16 + a_col_l;
            uint32_t ah0[4], al0[4], ah1[4], al1[4];
            ldm_x4(ah0, sAh + ((wm * 32 + a_row_l) * GPAD + col) * 2);
            ldm_x4(al0, sAl + ((wm * 32 + a_row_l) * GPAD + col) * 2);
            ldm_x4(ah1, sAh + ((wm * 32 + 16 + a_row_l) * GPAD + col) * 2);
            ldm_x4(al1, sAl + ((wm * 32 + 16 + a_row_l) * GPAD + col) * 2);
            if (kk < 3) loadB(cur ^ 1, kk + 1);
            #pragma unroll
            for (int ni = 0; ni < 4; ++ni) {
                mma_bf16(acc[0][ni], ah0, BHf[cur][ni]);
                mma_bf16(acc[0][ni], ah0, BLf[cur][ni]);
                mma_bf16(acc[0][ni], al0, BHf[cur][ni]);
                mma_bf16(acc[1][ni], ah1, BHf[cur][ni]);
                mma_bf16(acc[1][ni], ah1, BLf[cur][ni]);
                mma_bf16(acc[1][ni], al1, BHf[cur][ni]);
            }
        }
    }

    __nv_bfloat16* Ch = FUSED ? (z == 0 ? Ch0 : (z == 1 ? Ch1 : Ch2)) : Ch0;
    __nv_bfloat16* Cl = FUSED ? (z == 0 ? Cl0 : (z == 1 ? Cl1 : Cl2)) : Cl0;
    const bool do_rope = FUSED && (z < 2);

    const int lr = lane >> 2;
    const int lc = (lane & 3) * 2;

    #pragma unroll
    for (int mi = 0; mi < 2; ++mi) {
        #pragma unroll
        for (int half = 0; half < 2; ++half) {
            const int m = bm + wm * 32 + mi * 16 + lr + half * 8;
            const int s_pos = m & (Ss - 1);
            const int b_idx = m >> 11;
            #pragma unroll
            for (int ni = 0; ni < 4; ++ni) {
                const int nl = wn * 32 + ni * 8 + lc;
                const int n = bn + nl;
                float f0 = acc[mi][ni][half * 2 + 0] + sbias[nl];
                float f1 = acc[mi][ni][half * 2 + 1] + sbias[nl + 1];

                if (do_rope) {
                    const int d0 = n & 63;
                    const int j0 = d0 & 31;
                    const int j1 = (d0 + 1) & 31;
                    const float inv0 = 1.0f / powf(10000.0f, (float)j0 * (1.0f / 32.0f));
                    const float inv1 = 1.0f / powf(10000.0f, (float)j1 * (1.0f / 32.0f));
                    float s0, c0, s1, c1;
                    sincosf((float)s_pos * inv0, &s0, &c0);
                    sincosf((float)s_pos * inv1, &s1, &c1);
                    const float x0 = f0, x1 = f1;
                    f0 = x0 * c0 - x1 * s1;
                    f1 = x0 * s0 + x1 * c1;
                }

                if (FUSED) {
                    const int h = n >> 6, d = n & 63;
                    const size_t idx =
                        (((size_t)b_idx * Hh + h) * Ss + s_pos) * DKk + d;
                    const __nv_bfloat16 h0 = __float2bfloat16_rn(f0);
                    const __nv_bfloat16 h1 = __float2bfloat16_rn(f1);
                    *(uint32_t*)(Ch + idx) = pack2(h0, h1);
                    *(uint32_t*)(Cl + idx) =
                        pack2(__float2bfloat16_rn(f0 - __bfloat162float(h0)),
                              __float2bfloat16_rn(f1 - __bfloat162float(h1)));
                } else {
                    *(float2*)(Cf + (size_t)m * Dd + n) = make_float2(f0, f1);
                }
            }
        }
    }
}

// ---------------------------------------------------------------------------
// Causal flash attention, fragment-double-buffered, 128-key blocks.
// ---------------------------------------------------------------------------
#define ASTAGE (4 * 128 * GPAD)

__global__ __launch_bounds__(256, 1) void attn_mma()
{
    extern __shared__ __nv_bfloat16 smb[];
    __nv_bfloat16* Qh = smb;
    __nv_bfloat16* Ql = Qh + 128 * GPAD;
    __nv_bfloat16* Stg = Ql + 128 * GPAD;

    const int qb = gridDim.x - 1 - blockIdx.x;
    const int bh = blockIdx.y;
    const int bidx = bh >> 4;
    const int head = bh & 15;
    const int tid = threadIdx.x;
    const int lane = tid & 31;
    const int w = tid >> 5;
    const int wq = w * 16;

    const __nv_bfloat16* qhg = g_qh + ((size_t)bh * Ss + (size_t)qb * 128) * DKk;
    const __nv_bfloat16* qlg = g_ql + ((size_t)bh * Ss + (size_t)qb * 128) * DKk;
    const __nv_bfloat16* khg = g_kh + (size_t)bh * Ss * DKk;
    const __nv_bfloat16* klg = g_kl + (size_t)bh * Ss * DKk;
    const __nv_bfloat16* vhg = g_vh + (size_t)bh * Ss * DKk;
    const __nv_bfloat16* vlg = g_vl + (size_t)bh * Ss * DKk;

    const uint32_t sQh = smem_u32(Qh), sQl = smem_u32(Ql);
    const uint32_t sStg = smem_u32(Stg);

    #pragma unroll
    for (int e = tid; e < 1024; e += 256) {
        const int r = e >> 3, c = (e & 7) * 8;
        *(uint4*)(Qh + r * GPAD + c) = *(const uint4*)(qhg + r * 64 + c);
        *(uint4*)(Ql + r * GPAD + c) = *(const uint4*)(qlg + r * 64 + c);
    }

    const int nkb = qb + 1;

    const int f_r = tid >> 3;
    const int f_c = (tid & 7) * 8;
    auto fill_stage = [&](int stage, int kb) {
        const size_t gofs = (size_t)kb * 128 * DKk;
        const uint32_t sb = sStg + stage * ASTAGE * 2;
        #pragma unroll
        for (int i = 0; i < 4; ++i) {
            const int r = f_r + i * 32;
            const uint32_t so = (r * GPAD + f_c) * 2;
            const size_t go = gofs + r * 64 + f_c;
            CP16(sb + 0 * 128 * GPAD * 2 + so, khg + go);
            CP16(sb + 1 * 128 * GPAD * 2 + so, klg + go);
            CP16(sb + 2 * 128 * GPAD * 2 + so, vhg + go);
            CP16(sb + 3 * 128 * GPAD * 2 + so, vlg + go);
        }
        CP_COMMIT();
    };

    fill_stage(0, 0);
    __syncthreads();

    const int a_row = lane & 15;
    const int a_col = (lane & 16) >> 1;
    const int b_row = (lane & 7) + ((lane & 16) >> 1);
    const int b_col = lane & 8;
    const int v_key = ((lane >> 3) & 1) * 8 + (lane & 7);
    const int v_dim = (lane >> 4) * 8;

    uint32_t qfh[4][4], qfl[4][4];
    #pragma unroll
    for (int kt = 0; kt < 4; ++kt) {
        const uint32_t off = ((wq + a_row) * GPAD + kt * 16 + a_col) * 2;
        ldm_x4(qfh[kt], sQh + off);
        ldm_x4(qfl[kt], sQl + off);
    }

    float O[8][4];
    #pragma unroll
    for (int nf = 0; nf < 8; ++nf)
        #pragma unroll
        for (int j = 0; j < 4; ++j) O[nf][j] = 0.f;
    float mrow[2] = {-INFINITY, -INFINITY};
    float lrow[2] = {0.f, 0.f};

    const int lr = lane >> 2;
    const int lc2 = (lane & 3) * 2;
    const int q0 = qb * 128 + wq + lr;

    for (int kb = 0; kb < nkb; ++kb) {
        const int st = kb & 1;
        CP_WAIT0();
        __syncthreads();
        if (kb + 1 < nkb) fill_stage(st ^ 1, kb + 1);

        const uint32_t sKh = sStg + (st * ASTAGE + 0 * 128 * GPAD) * 2;
        const uint32_t sKl = sStg + (st * ASTAGE + 1 * 128 * GPAD) * 2;
        const uint32_t sVh = sStg + (st * ASTAGE + 2 * 128 * GPAD) * 2;
        const uint32_t sVl = sStg + (st * ASTAGE + 3 * 128 * GPAD) * 2;

        // ---- scores = Q K^T, flattened & fragment-double-buffered ----
        float acc[16][4];
        #pragma unroll
        for (int nf = 0; nf < 16; ++nf)
            #pragma unroll
            for (int j = 0; j < 4; ++j) acc[nf][j] = 0.f;

        {
            uint32_t KHf[2][2][2], KLf[2][2][2];
            auto loadK = [&](int buf, int it2) {
                const int kt2 = it2 >> 3, ntp2 = it2 & 7;
                const uint32_t off =
                    ((ntp2 * 16 + b_row) * GPAD + kt2 * 16 + b_col) * 2;
                uint32_t r4[4];
                ldm_x4(r4, sKh + off);
                KHf[buf][0][0] = r4[0]; KHf[buf][0][1] = r4[1];
                KHf[buf][1][0] = r4[2]; KHf[buf][1][1] = r4[3];
                ldm_x4(r4, sKl + off);
                KLf[buf][0][0] = r4[0]; KLf[buf][0][1] = r4[1];
                KLf[buf][1][0] = r4[2]; KLf[buf][1][1] = r4[3];
            };
            loadK(0, 0);
            #pragma unroll
            for (int it = 0; it < 32; ++it) {
                const int kt = it >> 3, ntp = it & 7, cur = it & 1;
                if (it < 31) loadK(cur ^ 1, it + 1);
                mma_bf16(acc[2*ntp],   qfh[kt], KHf[cur][0]);
                mma_bf16(acc[2*ntp],   qfh[kt], KLf[cur][0]);
                mma_bf16(acc[2*ntp],   qfl[kt], KHf[cur][0]);
                mma_bf16(acc[2*ntp+1], qfh[kt], KHf[cur][1]);
                mma_bf16(acc[2*ntp+1], qfh[kt], KLf[cur][1]);
                mma_bf16(acc[2*ntp+1], qfl[kt], KHf[cur][1]);
            }
        }

        // ---- scale + causal mask ----
        const bool diag = (kb == qb);
        #pragma unroll
        for (int nf = 0; nf < 16; ++nf) {
            #pragma unroll
            for (int j = 0; j < 4; ++j) {
                const float v = acc[nf][j] * 0.125f;
                if (diag) {
                    const int kgl = kb * 128 + nf * 8 + lc2 + (j & 1);
                    const int qgl = q0 + 8 * (j >> 1);
                    acc[nf][j] = (kgl <= qgl) ? v : -1e30f;
                } else {
                    acc[nf][j] = v;
                }
            }
        }

        // ---- online softmax (per row-half) ----
        #pragma unroll
        for (int half = 0; half < 2; ++half) {
            float rm = -1e30f;
            #pragma unroll
            for (int nf = 0; nf < 16; ++nf)
                rm = fmaxf(rm, fmaxf(acc[nf][2*half], acc[nf][2*half+1]));
            rm = fmaxf(rm, __shfl_xor_sync(0xffffffffu, rm, 1));
            rm = fmaxf(rm, __shfl_xor_sync(0xffffffffu, rm, 2));
            const float mn = fmaxf(mrow[half], rm);
            const float alpha = __expf(mrow[half] - mn);
            mrow[half] = mn;
            float rs = 0.f;
            #pragma unroll
            for (int nf = 0; nf < 16; ++nf) {
                const float p0 = __expf(acc[nf][2*half]   - mn);
                const float p1 = __expf(acc[nf][2*half+1] - mn);
                acc[nf][2*half]   = p0;
                acc[nf][2*half+1] = p1;
                rs += p0 + p1;
            }
            rs += __shfl_xor_sync(0xffffffffu, rs, 1);
            rs += __shfl_xor_sync(0xffffffffu, rs, 2);
            lrow[half] = lrow[half] * alpha + rs;
            #pragma unroll
            for (int nf = 0; nf < 8; ++nf) {
                O[nf][2*half]   *= alpha;
                O[nf][2*half+1] *= alpha;
            }
        }

        // ---- O += P V, flattened & fragment-double-buffered ----
        {
            uint32_t VHf[2][2][2], VLf[2][2][2];
            uint32_t ah[4], al[4];
            auto loadV = [&](int buf, int it2) {
                const int kt2 = it2 >> 2, nd2 = it2 & 3;
                const uint32_t off =
                    ((kt2 * 16 + v_key) * GPAD + nd2 * 16 + v_dim) * 2;
                uint32_t r4[4];
                ldm_x4_t(r4, sVh + off);
                VHf[buf][0][0] = r4[0]; VHf[buf][0][1] = r4[1];
                VHf[buf][1][0] = r4[2]; VHf[buf][1][1] = r4[3];
                ldm_x4_t(r4, sVl + off);
                VLf[buf][0][0] = r4[0]; VLf[buf][0][1] = r4[1];
                VLf[buf][1][0] = r4[2]; VLf[buf][1][1] = r4[3];
            };
            auto packP = [&](int kt) {
                #pragma unroll
                for (int f = 0; f < 4; ++f) {
                    const float p0 = acc[2*kt + (f >> 1)][(f & 1) * 2 + 0];
                    const float p1 = acc[2*kt + (f >> 1)][(f & 1) * 2 + 1];
                    const __nv_bfloat16 h0 = __float2bfloat16_rn(p0);
                    const __nv_bfloat16 h1 = __float2bfloat16_rn(p1);
                    ah[f] = pack2(h0, h1);
                    al[f] = pack2(__float2bfloat16_rn(p0 - __bfloat162float(h0)),
                                  __float2bfloat16_rn(p1 - __bfloat162float(h1)));
                }
            };
            packP(0);
            loadV(0, 0);
            #pragma unroll
            for (int it = 0; it < 32; ++it) {
                const int kt = it >> 2, nd = it & 3, cur = it & 1;
                if (it < 31) loadV(cur ^ 1, it + 1);
                mma_bf16(O[2*nd],   ah, VHf[cur][0]);
                mma_bf16(O[2*nd],   ah, VLf[cur][0]);
                mma_bf16(O[2*nd],   al, VHf[cur][0]);
                mma_bf16(O[2*nd+1], ah, VHf[cur][1]);
                mma_bf16(O[2*nd+1], ah, VLf[cur][1]);
                mma_bf16(O[2*nd+1], al, VHf[cur][1]);
                if (nd == 3 && kt < 7) packP(kt + 1);
            }
        }
    }

    // ---- normalize + split-store ----
    #pragma unroll
    for (int half = 0; half < 2; ++half) {
        const int qgl = q0 + 8 * half;
        const float inv = 1.0f / lrow[half];
        const size_t base = ((size_t)bidx * Ss + qgl) * Dd + head * 64;
        #pragma unroll
        for (int nf = 0; nf < 8; ++nf) {
            const float f0 = O[nf][2*half] * inv;
            const float f1 = O[nf][2*half+1] * inv;
            const __nv_bfloat16 h0 = __float2bfloat16_rn(f0);
            const __nv_bfloat16 h1 = __float2bfloat16_rn(f1);
            *(uint32_t*)(g_ath + base + nf * 8 + lc2) = pack2(h0, h1);
            *(uint32_t*)(g_atl + base + nf * 8 + lc2) =
                pack2(__float2bfloat16_rn(f0 - __bfloat162float(h0)),
                      __float2bfloat16_rn(f1 - __bfloat162float(h1)));
        }
    }
}

// ---------------------------------------------------------------------------
extern "C" void kernel_launch(void* const* d_in, const int* in_sizes, int n_in,
                              void* d_out, int out_size)
{
    const float* query = (const float*)d_in[0];
    const float* key   = (const float*)d_in[1];
    const float* value = (const float*)d_in[2];
    const float* Wq = (const float*)d_in[3];
    const float* bq = (const float*)d_in[4];
    const float* Wk = (const float*)d_in[5];
    const float* bk = (const float*)d_in[6];
    const float* Wv = (const float*)d_in[7];
    const float* bv = (const float*)d_in[8];
    const float* Wo = (const float*)d_in[9];
    const float* bo = (const float*)d_in[10];
    float* out = (float*)d_out;

    __nv_bfloat16 *qh, *ql, *kh, *kl, *vh, *vl, *ath, *atl, *wth, *wtl, *ish, *isl;
    cudaGetSymbolAddress((void**)&qh, g_qh);
    cudaGetSymbolAddress((void**)&ql, g_ql);
    cudaGetSymbolAddress((void**)&kh, g_kh);
    cudaGetSymbolAddress((void**)&kl, g_kl);
    cudaGetSymbolAddress((void**)&vh, g_vh);
    cudaGetSymbolAddress((void**)&vl, g_vl);
    cudaGetSymbolAddress((void**)&ath, g_ath);
    cudaGetSymbolAddress((void**)&atl, g_atl);
    cudaGetSymbolAddress((void**)&wth, g_wth);
    cudaGetSymbolAddress((void**)&wtl, g_wtl);
    cudaGetSymbolAddress((void**)&ish, g_insh);
    cudaGetSymbolAddress((void**)&isl, g_insl);

    transpose_split4<<<dim3(32, 32, 4), dim3(32, 8)>>>(Wq, Wk, Wv, Wo, wth, wtl);
    split_inputs<<<dim3(4096, 1, 3), 256>>>(query, key, value);

    const int gsmem = 2 * GSTAGE * (int)sizeof(__nv_bfloat16);   // 147456
    cudaFuncSetAttribute(gemm_mma<1>, cudaFuncAttributeMaxDynamicSharedMemorySize, gsmem);
    cudaFuncSetAttribute(gemm_mma<0>, cudaFuncAttributeMaxDynamicSharedMemorySize, gsmem);

    // Fused QKV projection: grid.x = 3 weights x 8 n-tiles
    gemm_mma<1><<<dim3(24, 32), 512, gsmem>>>(
        ish, isl, wth, wtl, bq, bk, bv, nullptr,
        qh, ql, kh, kl, vh, vl);

    const int asmem = (2 * 128 * GPAD + 2 * ASTAGE) *
                      (int)sizeof(__nv_bfloat16);   // 184320
    cudaFuncSetAttribute(attn_mma, cudaFuncAttributeMaxDynamicSharedMemorySize, asmem);
    attn_mma<<<dim3(Ss / 128, Bb * Hh), 256, asmem>>>();

    // Output projection (fp32 out)
    gemm_mma<0><<<dim3(8, 32), 512, gsmem>>>(
        ath, atl, wth + 3u * 1048576, wtl + 3u * 1048576, bo, nullptr, nullptr,
        out, nullptr, nullptr, nullptr, nullptr, nullptr, nullptr);
}